// round 10
// baseline (speedup 1.0000x reference)
#include <cuda_runtime.h>
#include <math.h>

#define Nn   50000
#define Ee   800000
#define E2c  850000      // E + N self-loops
#define NG   64
#define NCLS 10

// ---------------- device scratch ----------------
__device__ float g_h[(size_t)Nn * 128];     // per-layer GEMM output  [N,128]
__device__ float g_out[(size_t)Nn * 128];   // per-layer aggregation  [N,128] (normalized)
__device__ float g_asrc[Nn * 2];            // alpha_src  [N,H]
__device__ float g_adst[Nn * 2];            // alpha_dst  [N,H]
__device__ int   g_deg[Nn];                 // degree counts
__device__ int   g_rowptr[Nn + 1];          // CSR row offsets
__device__ int   g_cursor[Nn];              // fill cursors
__device__ int   g_eidx[E2c];               // src node per CSR slot
__device__ float g_pool[NG * 128];
__device__ float g_cnt[NG];
__device__ int   g_is64;

// ---------------- helpers ----------------
__device__ __forceinline__ float eluf(float v) { return v > 0.f ? v : expm1f(v); }
__device__ __forceinline__ int loadIdx(const void* p, int i) {
    if (g_is64) return (int)((const long long*)p)[i];
    return ((const int*)p)[i];
}
__device__ __forceinline__ void red_add_v4(float* dst, float4 v) {
    asm volatile("red.global.add.v4.f32 [%0], {%1,%2,%3,%4};"
                 :: "l"(dst), "f"(v.x), "f"(v.y), "f"(v.z), "f"(v.w) : "memory");
}

// ---------------- dtype detection (int32 vs int64 edge indices) ----------------
__global__ void detect_kernel(const int* ei32) {
    __shared__ int sh;
    if (threadIdx.x == 0) sh = 0;
    __syncthreads();
    int v = 0;
    for (int i = threadIdx.x; i < 2048; i += 256) v |= ei32[2 * i + 1];
    atomicOr(&sh, v);
    __syncthreads();
    if (threadIdx.x == 0) g_is64 = (sh == 0) ? 1 : 0;
}

// ---------------- CSR build ----------------
__global__ void zero_deg_kernel() {
    int i = blockIdx.x * blockDim.x + threadIdx.x;
    if (i < Nn) g_deg[i] = 0;
}

__global__ void degree_kernel(const void* __restrict__ ei) {
    int e = blockIdx.x * blockDim.x + threadIdx.x;
    if (e >= E2c) return;
    int d = (e < Ee) ? loadIdx(ei, Ee + e) : (e - Ee);
    atomicAdd(&g_deg[d], 1);
}

__global__ void scan_kernel() {
    __shared__ int sh[1024];
    __shared__ int carry;
    int tid = threadIdx.x;
    if (tid == 0) carry = 0;
    __syncthreads();
    for (int chunk = 0; chunk < Nn; chunk += 1024) {
        int idx = chunk + tid;
        int v = (idx < Nn) ? g_deg[idx] : 0;
        sh[tid] = v;
        __syncthreads();
        for (int o = 1; o < 1024; o <<= 1) {
            int t = (tid >= o) ? sh[tid - o] : 0;
            __syncthreads();
            sh[tid] += t;
            __syncthreads();
        }
        int excl = carry + sh[tid] - v;
        if (idx < Nn) { g_rowptr[idx] = excl; g_cursor[idx] = excl; }
        __syncthreads();
        if (tid == 0) carry += sh[1023];
        __syncthreads();
    }
    if (tid == 0) g_rowptr[Nn] = carry;
}

__global__ void fill_kernel(const void* __restrict__ ei) {
    int e = blockIdx.x * blockDim.x + threadIdx.x;
    if (e >= E2c) return;
    int s, d;
    if (e < Ee) { s = loadIdx(ei, e); d = loadIdx(ei, Ee + e); }
    else        { s = e - Ee; d = s; }
    int pos = atomicAdd(&g_cursor[d], 1);
    g_eidx[pos] = s;
}

// ---------------- GEMM + fused alpha epilogue ----------------
// MODE 0: X = raw input. MODE 1: X = elu(g_out + biasPrev) (g_out pre-normalized)
template <int MODE>
__global__ void gemm_kernel(const float* __restrict__ X,
                            const float* __restrict__ Wm,
                            const float* __restrict__ biasPrev,
                            const float* __restrict__ attS,
                            const float* __restrict__ attD) {
    __shared__ float As[16][128];   // [k][m]
    __shared__ float Bs[16][128];   // [k][n]
    const int tid = threadIdx.x;
    const int bm  = blockIdx.x * 128;
    const int tx  = tid & 15;
    const int ty  = tid >> 4;
    float acc[8][8];
#pragma unroll
    for (int i = 0; i < 8; i++)
#pragma unroll
        for (int j = 0; j < 8; j++) acc[i][j] = 0.f;

    for (int k0 = 0; k0 < 128; k0 += 16) {
#pragma unroll
        for (int t = 0; t < 2; t++) {
            int e   = tid + t * 256;
            int row = e >> 2;
            int kk4 = (e & 3) << 2;
            int gr  = bm + row;
            float4 v = make_float4(0.f, 0.f, 0.f, 0.f);
            if (gr < Nn) {
                if (MODE == 0) {
                    v = *(const float4*)(X + (size_t)gr * 128 + k0 + kk4);
                } else {
                    v = *(const float4*)(g_out + (size_t)gr * 128 + k0 + kk4);
                    v.x = eluf(v.x + biasPrev[k0 + kk4 + 0]);
                    v.y = eluf(v.y + biasPrev[k0 + kk4 + 1]);
                    v.z = eluf(v.z + biasPrev[k0 + kk4 + 2]);
                    v.w = eluf(v.w + biasPrev[k0 + kk4 + 3]);
                }
            }
            As[kk4 + 0][row] = v.x;
            As[kk4 + 1][row] = v.y;
            As[kk4 + 2][row] = v.z;
            As[kk4 + 3][row] = v.w;
            int kb = e >> 5;
            int n4 = (e & 31) << 2;
            *(float4*)&Bs[kb][n4] = *(const float4*)(Wm + (size_t)(k0 + kb) * 128 + n4);
        }
        __syncthreads();
#pragma unroll
        for (int kk = 0; kk < 16; kk++) {
            float a[8], b[8];
            *(float4*)&a[0] = *(const float4*)&As[kk][ty * 8];
            *(float4*)&a[4] = *(const float4*)&As[kk][ty * 8 + 4];
            *(float4*)&b[0] = *(const float4*)&Bs[kk][tx * 8];
            *(float4*)&b[4] = *(const float4*)&Bs[kk][tx * 8 + 4];
#pragma unroll
            for (int i = 0; i < 8; i++)
#pragma unroll
                for (int j = 0; j < 8; j++)
                    acc[i][j] = fmaf(a[i], b[j], acc[i][j]);
        }
        __syncthreads();
    }

    // store h
#pragma unroll
    for (int i = 0; i < 8; i++) {
        int gr = bm + ty * 8 + i;
        if (gr < Nn) {
            *(float4*)(g_h + (size_t)gr * 128 + tx * 8) =
                make_float4(acc[i][0], acc[i][1], acc[i][2], acc[i][3]);
            *(float4*)(g_h + (size_t)gr * 128 + tx * 8 + 4) =
                make_float4(acc[i][4], acc[i][5], acc[i][6], acc[i][7]);
        }
    }

    // fused alpha: this thread's 8 cols (tx*8..tx*8+7) lie in one head (tx<8 -> head0)
    float as[8], ad[8];
    *(float4*)&as[0] = *(const float4*)(attS + tx * 8);
    *(float4*)&as[4] = *(const float4*)(attS + tx * 8 + 4);
    *(float4*)&ad[0] = *(const float4*)(attD + tx * 8);
    *(float4*)&ad[4] = *(const float4*)(attD + tx * 8 + 4);
    int head = tx >> 3;
#pragma unroll
    for (int i = 0; i < 8; i++) {
        float s = 0.f, d = 0.f;
#pragma unroll
        for (int j = 0; j < 8; j++) {
            s = fmaf(acc[i][j], as[j], s);
            d = fmaf(acc[i][j], ad[j], d);
        }
#pragma unroll
        for (int o = 4; o; o >>= 1) {
            s += __shfl_xor_sync(0xFFFFFFFFu, s, o);
            d += __shfl_xor_sync(0xFFFFFFFFu, d, o);
        }
        if ((tx & 7) == 0) {
            int gr = bm + ty * 8 + i;
            if (gr < Nn) {
                g_asrc[gr * 2 + head] = s;
                g_adst[gr * 2 + head] = d;
            }
        }
    }
}

// ---------------- fused edge softmax + aggregate (warp per dst node) ----------------
__global__ void aggregate_kernel() {
    int gid  = blockIdx.x * blockDim.x + threadIdx.x;
    int n    = gid >> 5;
    if (n >= Nn) return;
    int lane = gid & 31;
    int hh   = lane >> 4;

    float ad0 = g_adst[n * 2 + 0];
    float ad1 = g_adst[n * 2 + 1];
    int start = g_rowptr[n];
    int end   = g_rowptr[n + 1];

    float z0 = 0.f, z1 = 0.f;
    float4 accA = make_float4(0.f, 0.f, 0.f, 0.f);
    float4 accB = make_float4(0.f, 0.f, 0.f, 0.f);

    for (int base = start; base < end; base += 32) {
        int i = base + lane;
        int s = 0; float p0 = 0.f, p1 = 0.f;
        if (i < end) {
            s = g_eidx[i];
            float l0 = g_asrc[s * 2 + 0] + ad0; l0 = l0 > 0.f ? l0 : 0.2f * l0;
            float l1 = g_asrc[s * 2 + 1] + ad1; l1 = l1 > 0.f ? l1 : 0.2f * l1;
            p0 = __expf(l0); p1 = __expf(l1);
            z0 += p0; z1 += p1;
        }
        int cnt = min(32, end - base);
        int j = 0;
        for (; j + 1 < cnt; j += 2) {
            int   sA  = __shfl_sync(0xFFFFFFFFu, s, j);
            float pA0 = __shfl_sync(0xFFFFFFFFu, p0, j);
            float pA1 = __shfl_sync(0xFFFFFFFFu, p1, j);
            int   sB  = __shfl_sync(0xFFFFFFFFu, s, j + 1);
            float pB0 = __shfl_sync(0xFFFFFFFFu, p0, j + 1);
            float pB1 = __shfl_sync(0xFFFFFFFFu, p1, j + 1);
            float pA = hh ? pA1 : pA0;
            float pB = hh ? pB1 : pB0;
            float4 hA = *(const float4*)(g_h + (size_t)sA * 128 + lane * 4);
            float4 hB = *(const float4*)(g_h + (size_t)sB * 128 + lane * 4);
            accA.x = fmaf(pA, hA.x, accA.x); accA.y = fmaf(pA, hA.y, accA.y);
            accA.z = fmaf(pA, hA.z, accA.z); accA.w = fmaf(pA, hA.w, accA.w);
            accB.x = fmaf(pB, hB.x, accB.x); accB.y = fmaf(pB, hB.y, accB.y);
            accB.z = fmaf(pB, hB.z, accB.z); accB.w = fmaf(pB, hB.w, accB.w);
        }
        if (j < cnt) {
            int   sA  = __shfl_sync(0xFFFFFFFFu, s, j);
            float pA0 = __shfl_sync(0xFFFFFFFFu, p0, j);
            float pA1 = __shfl_sync(0xFFFFFFFFu, p1, j);
            float pA = hh ? pA1 : pA0;
            float4 hA = *(const float4*)(g_h + (size_t)sA * 128 + lane * 4);
            accA.x = fmaf(pA, hA.x, accA.x); accA.y = fmaf(pA, hA.y, accA.y);
            accA.z = fmaf(pA, hA.z, accA.z); accA.w = fmaf(pA, hA.w, accA.w);
        }
    }
#pragma unroll
    for (int o = 16; o; o >>= 1) {
        z0 += __shfl_xor_sync(0xFFFFFFFFu, z0, o);
        z1 += __shfl_xor_sync(0xFFFFFFFFu, z1, o);
    }
    float inv = 1.0f / (hh ? z1 : z0);
    float4 r;
    r.x = (accA.x + accB.x) * inv;
    r.y = (accA.y + accB.y) * inv;
    r.z = (accA.z + accB.z) * inv;
    r.w = (accA.w + accB.w) * inv;
    *(float4*)(g_out + (size_t)n * 128 + lane * 4) = r;
}

// ---------------- pooling ----------------
__global__ void init_pool_kernel() {
    int i = blockIdx.x * blockDim.x + threadIdx.x;
    if (i < NG * 128) g_pool[i] = 0.f;
    if (i < NG) g_cnt[i] = 0.f;
}

__global__ void pool_kernel(const void* __restrict__ batch,
                            const float* __restrict__ bias2) {
    int gid  = blockIdx.x * blockDim.x + threadIdx.x;
    int n    = gid >> 5;
    int lane = gid & 31;
    if (n >= Nn) return;
    int g = loadIdx(batch, n);
    float4 v = *(const float4*)(g_out + (size_t)n * 128 + lane * 4);
    const float* bp = bias2 + lane * 4;
    v.x = eluf(v.x + bp[0]);
    v.y = eluf(v.y + bp[1]);
    v.z = eluf(v.z + bp[2]);
    v.w = eluf(v.w + bp[3]);
    red_add_v4(g_pool + g * 128 + lane * 4, v);
    if (lane == 0) atomicAdd(&g_cnt[g], 1.0f);
}

// ---------------- classifier head + softmax ----------------
__global__ void head_kernel(const float* __restrict__ lw,
                            const float* __restrict__ lb,
                            float* __restrict__ out) {
    int g = threadIdx.x;
    if (g >= NG) return;
    float inv = 1.0f / fmaxf(g_cnt[g], 1.0f);
    float lg[NCLS];
#pragma unroll
    for (int c = 0; c < NCLS; c++) lg[c] = lb[c];
    for (int k = 0; k < 128; k++) {
        float pv = g_pool[g * 128 + k] * inv;
#pragma unroll
        for (int c = 0; c < NCLS; c++) lg[c] = fmaf(pv, lw[k * NCLS + c], lg[c]);
    }
    float mx = lg[0];
#pragma unroll
    for (int c = 1; c < NCLS; c++) mx = fmaxf(mx, lg[c]);
    float ssum = 0.f;
#pragma unroll
    for (int c = 0; c < NCLS; c++) { lg[c] = __expf(lg[c] - mx); ssum += lg[c]; }
    float is = 1.0f / ssum;
#pragma unroll
    for (int c = 0; c < NCLS; c++) out[g * NCLS + c] = lg[c] * is;
}

// ---------------- launch ----------------
extern "C" void kernel_launch(void* const* d_in, const int* in_sizes, int n_in,
                              void* d_out, int out_size) {
    const float* x    = (const float*)d_in[0];
    const void*  ei   = d_in[1];
    const void*  bat  = d_in[2];
    const float* W    = (const float*)d_in[3];
    const float* asrc = (const float*)d_in[4];
    const float* adst = (const float*)d_in[5];
    const float* bias = (const float*)d_in[6];
    const float* lw   = (const float*)d_in[7];
    const float* lb   = (const float*)d_in[8];

    const int gemmBlocks     = (Nn + 127) / 128;
    const int nodeWarpBlocks = (Nn * 32 + 255) / 256;
    const int edgeBlocks     = (E2c + 255) / 256;
    const int nodeBlocks     = (Nn + 255) / 256;

    detect_kernel<<<1, 256>>>((const int*)ei);

    // CSR build (once per launch)
    zero_deg_kernel<<<nodeBlocks, 256>>>();
    degree_kernel<<<edgeBlocks, 256>>>(ei);
    scan_kernel<<<1, 1024>>>();
    fill_kernel<<<edgeBlocks, 256>>>(ei);

    for (int l = 0; l < 3; l++) {
        if (l == 0)
            gemm_kernel<0><<<gemmBlocks, 256>>>(x, W, nullptr,
                                                asrc, adst);
        else
            gemm_kernel<1><<<gemmBlocks, 256>>>(nullptr, W + l * 16384,
                                                bias + (l - 1) * 128,
                                                asrc + l * 128, adst + l * 128);
        aggregate_kernel<<<nodeWarpBlocks, 256>>>();
    }
    init_pool_kernel<<<(NG * 128 + 255) / 256, 256>>>();
    pool_kernel<<<nodeWarpBlocks, 256>>>(bat, bias + 2 * 128);
    head_kernel<<<1, 64>>>(lw, lb, (float*)d_out);
}

// round 11
// speedup vs baseline: 1.0056x; 1.0056x over previous
#include <cuda_runtime.h>
#include <math.h>

#define Nn   50000
#define Ee   800000
#define E2c  850000      // E + N self-loops
#define NG   64
#define NCLS 10

// ---------------- device scratch ----------------
__device__ float g_h[(size_t)Nn * 128];     // per-layer GEMM output  [N,128]
__device__ float g_out[(size_t)Nn * 128];   // per-layer aggregation  [N,128] (normalized)
__device__ float g_asrc[Nn * 2];            // alpha_src  [N,H]
__device__ float g_adst[Nn * 2];            // alpha_dst  [N,H]
__device__ int   g_deg[Nn];                 // degree counts
__device__ int   g_rowptr[Nn + 1];          // CSR row offsets
__device__ int   g_cursor[Nn];              // fill cursors
__device__ int   g_eidx[E2c];               // src node per CSR slot
__device__ float g_pool[NG * 128];
__device__ float g_cnt[NG];
__device__ int   g_is64;

// ---------------- helpers ----------------
__device__ __forceinline__ float eluf(float v) { return v > 0.f ? v : expm1f(v); }
__device__ __forceinline__ int loadIdx(const void* p, int i) {
    if (g_is64) return (int)((const long long*)p)[i];
    return ((const int*)p)[i];
}
__device__ __forceinline__ void red_add_v4(float* dst, float4 v) {
    asm volatile("red.global.add.v4.f32 [%0], {%1,%2,%3,%4};"
                 :: "l"(dst), "f"(v.x), "f"(v.y), "f"(v.z), "f"(v.w) : "memory");
}

// ---------------- dtype detection (int32 vs int64 edge indices) ----------------
__global__ void detect_kernel(const int* ei32) {
    __shared__ int sh;
    if (threadIdx.x == 0) sh = 0;
    __syncthreads();
    int v = 0;
    for (int i = threadIdx.x; i < 2048; i += 256) v |= ei32[2 * i + 1];
    atomicOr(&sh, v);
    __syncthreads();
    if (threadIdx.x == 0) g_is64 = (sh == 0) ? 1 : 0;
}

// ---------------- CSR build ----------------
__global__ void zero_deg_kernel() {
    int i = blockIdx.x * blockDim.x + threadIdx.x;
    if (i < Nn) g_deg[i] = 0;
}

__global__ void degree_kernel(const void* __restrict__ ei) {
    int e = blockIdx.x * blockDim.x + threadIdx.x;
    if (e >= E2c) return;
    int d = (e < Ee) ? loadIdx(ei, Ee + e) : (e - Ee);
    atomicAdd(&g_deg[d], 1);
}

__global__ void scan_kernel() {
    __shared__ int sh[1024];
    __shared__ int carry;
    int tid = threadIdx.x;
    if (tid == 0) carry = 0;
    __syncthreads();
    for (int chunk = 0; chunk < Nn; chunk += 1024) {
        int idx = chunk + tid;
        int v = (idx < Nn) ? g_deg[idx] : 0;
        sh[tid] = v;
        __syncthreads();
        for (int o = 1; o < 1024; o <<= 1) {
            int t = (tid >= o) ? sh[tid - o] : 0;
            __syncthreads();
            sh[tid] += t;
            __syncthreads();
        }
        int excl = carry + sh[tid] - v;
        if (idx < Nn) { g_rowptr[idx] = excl; g_cursor[idx] = excl; }
        __syncthreads();
        if (tid == 0) carry += sh[1023];
        __syncthreads();
    }
    if (tid == 0) g_rowptr[Nn] = carry;
}

__global__ void fill_kernel(const void* __restrict__ ei) {
    int e = blockIdx.x * blockDim.x + threadIdx.x;
    if (e >= E2c) return;
    int s, d;
    if (e < Ee) { s = loadIdx(ei, e); d = loadIdx(ei, Ee + e); }
    else        { s = e - Ee; d = s; }
    int pos = atomicAdd(&g_cursor[d], 1);
    g_eidx[pos] = s;
}

// ---------------- GEMM + fused alpha epilogue ----------------
// MODE 0: X = raw input. MODE 1: X = elu(g_out + biasPrev) (g_out pre-normalized)
template <int MODE>
__global__ void gemm_kernel(const float* __restrict__ X,
                            const float* __restrict__ Wm,
                            const float* __restrict__ biasPrev,
                            const float* __restrict__ attS,
                            const float* __restrict__ attD) {
    __shared__ float As[16][128];   // [k][m]
    __shared__ float Bs[16][128];   // [k][n]
    const int tid = threadIdx.x;
    const int bm  = blockIdx.x * 128;
    const int tx  = tid & 15;
    const int ty  = tid >> 4;
    float acc[8][8];
#pragma unroll
    for (int i = 0; i < 8; i++)
#pragma unroll
        for (int j = 0; j < 8; j++) acc[i][j] = 0.f;

    for (int k0 = 0; k0 < 128; k0 += 16) {
#pragma unroll
        for (int t = 0; t < 2; t++) {
            int e   = tid + t * 256;
            int row = e >> 2;
            int kk4 = (e & 3) << 2;
            int gr  = bm + row;
            float4 v = make_float4(0.f, 0.f, 0.f, 0.f);
            if (gr < Nn) {
                if (MODE == 0) {
                    v = *(const float4*)(X + (size_t)gr * 128 + k0 + kk4);
                } else {
                    v = *(const float4*)(g_out + (size_t)gr * 128 + k0 + kk4);
                    v.x = eluf(v.x + biasPrev[k0 + kk4 + 0]);
                    v.y = eluf(v.y + biasPrev[k0 + kk4 + 1]);
                    v.z = eluf(v.z + biasPrev[k0 + kk4 + 2]);
                    v.w = eluf(v.w + biasPrev[k0 + kk4 + 3]);
                }
            }
            As[kk4 + 0][row] = v.x;
            As[kk4 + 1][row] = v.y;
            As[kk4 + 2][row] = v.z;
            As[kk4 + 3][row] = v.w;
            int kb = e >> 5;
            int n4 = (e & 31) << 2;
            *(float4*)&Bs[kb][n4] = *(const float4*)(Wm + (size_t)(k0 + kb) * 128 + n4);
        }
        __syncthreads();
#pragma unroll
        for (int kk = 0; kk < 16; kk++) {
            float a[8], b[8];
            *(float4*)&a[0] = *(const float4*)&As[kk][ty * 8];
            *(float4*)&a[4] = *(const float4*)&As[kk][ty * 8 + 4];
            *(float4*)&b[0] = *(const float4*)&Bs[kk][tx * 8];
            *(float4*)&b[4] = *(const float4*)&Bs[kk][tx * 8 + 4];
#pragma unroll
            for (int i = 0; i < 8; i++)
#pragma unroll
                for (int j = 0; j < 8; j++)
                    acc[i][j] = fmaf(a[i], b[j], acc[i][j]);
        }
        __syncthreads();
    }

    // store h
#pragma unroll
    for (int i = 0; i < 8; i++) {
        int gr = bm + ty * 8 + i;
        if (gr < Nn) {
            *(float4*)(g_h + (size_t)gr * 128 + tx * 8) =
                make_float4(acc[i][0], acc[i][1], acc[i][2], acc[i][3]);
            *(float4*)(g_h + (size_t)gr * 128 + tx * 8 + 4) =
                make_float4(acc[i][4], acc[i][5], acc[i][6], acc[i][7]);
        }
    }

    // fused alpha: this thread's 8 cols (tx*8..tx*8+7) lie in one head (tx<8 -> head0)
    float as[8], ad[8];
    *(float4*)&as[0] = *(const float4*)(attS + tx * 8);
    *(float4*)&as[4] = *(const float4*)(attS + tx * 8 + 4);
    *(float4*)&ad[0] = *(const float4*)(attD + tx * 8);
    *(float4*)&ad[4] = *(const float4*)(attD + tx * 8 + 4);
    int head = tx >> 3;
#pragma unroll
    for (int i = 0; i < 8; i++) {
        float s = 0.f, d = 0.f;
#pragma unroll
        for (int j = 0; j < 8; j++) {
            s = fmaf(acc[i][j], as[j], s);
            d = fmaf(acc[i][j], ad[j], d);
        }
#pragma unroll
        for (int o = 4; o; o >>= 1) {
            s += __shfl_xor_sync(0xFFFFFFFFu, s, o);
            d += __shfl_xor_sync(0xFFFFFFFFu, d, o);
        }
        if ((tx & 7) == 0) {
            int gr = bm + ty * 8 + i;
            if (gr < Nn) {
                g_asrc[gr * 2 + head] = s;
                g_adst[gr * 2 + head] = d;
            }
        }
    }
}

// ---------------- fused edge softmax + aggregate (warp per dst node) ----------------
__global__ void aggregate_kernel() {
    int gid  = blockIdx.x * blockDim.x + threadIdx.x;
    int n    = gid >> 5;
    if (n >= Nn) return;
    int lane = gid & 31;
    int hh   = lane >> 4;

    float ad0 = g_adst[n * 2 + 0];
    float ad1 = g_adst[n * 2 + 1];
    int start = g_rowptr[n];
    int end   = g_rowptr[n + 1];

    float z0 = 0.f, z1 = 0.f;
    float4 accA = make_float4(0.f, 0.f, 0.f, 0.f);
    float4 accB = make_float4(0.f, 0.f, 0.f, 0.f);

    for (int base = start; base < end; base += 32) {
        int i = base + lane;
        int s = 0; float p0 = 0.f, p1 = 0.f;
        if (i < end) {
            s = g_eidx[i];
            float l0 = g_asrc[s * 2 + 0] + ad0; l0 = l0 > 0.f ? l0 : 0.2f * l0;
            float l1 = g_asrc[s * 2 + 1] + ad1; l1 = l1 > 0.f ? l1 : 0.2f * l1;
            p0 = __expf(l0); p1 = __expf(l1);
            z0 += p0; z1 += p1;
        }
        int cnt = min(32, end - base);
        int j = 0;
        for (; j + 1 < cnt; j += 2) {
            int   sA  = __shfl_sync(0xFFFFFFFFu, s, j);
            float pA0 = __shfl_sync(0xFFFFFFFFu, p0, j);
            float pA1 = __shfl_sync(0xFFFFFFFFu, p1, j);
            int   sB  = __shfl_sync(0xFFFFFFFFu, s, j + 1);
            float pB0 = __shfl_sync(0xFFFFFFFFu, p0, j + 1);
            float pB1 = __shfl_sync(0xFFFFFFFFu, p1, j + 1);
            float pA = hh ? pA1 : pA0;
            float pB = hh ? pB1 : pB0;
            float4 hA = *(const float4*)(g_h + (size_t)sA * 128 + lane * 4);
            float4 hB = *(const float4*)(g_h + (size_t)sB * 128 + lane * 4);
            accA.x = fmaf(pA, hA.x, accA.x); accA.y = fmaf(pA, hA.y, accA.y);
            accA.z = fmaf(pA, hA.z, accA.z); accA.w = fmaf(pA, hA.w, accA.w);
            accB.x = fmaf(pB, hB.x, accB.x); accB.y = fmaf(pB, hB.y, accB.y);
            accB.z = fmaf(pB, hB.z, accB.z); accB.w = fmaf(pB, hB.w, accB.w);
        }
        if (j < cnt) {
            int   sA  = __shfl_sync(0xFFFFFFFFu, s, j);
            float pA0 = __shfl_sync(0xFFFFFFFFu, p0, j);
            float pA1 = __shfl_sync(0xFFFFFFFFu, p1, j);
            float pA = hh ? pA1 : pA0;
            float4 hA = *(const float4*)(g_h + (size_t)sA * 128 + lane * 4);
            accA.x = fmaf(pA, hA.x, accA.x); accA.y = fmaf(pA, hA.y, accA.y);
            accA.z = fmaf(pA, hA.z, accA.z); accA.w = fmaf(pA, hA.w, accA.w);
        }
    }
#pragma unroll
    for (int o = 16; o; o >>= 1) {
        z0 += __shfl_xor_sync(0xFFFFFFFFu, z0, o);
        z1 += __shfl_xor_sync(0xFFFFFFFFu, z1, o);
    }
    float inv = 1.0f / (hh ? z1 : z0);
    float4 r;
    r.x = (accA.x + accB.x) * inv;
    r.y = (accA.y + accB.y) * inv;
    r.z = (accA.z + accB.z) * inv;
    r.w = (accA.w + accB.w) * inv;
    *(float4*)(g_out + (size_t)n * 128 + lane * 4) = r;
}

// ---------------- pooling ----------------
__global__ void init_pool_kernel() {
    int i = blockIdx.x * blockDim.x + threadIdx.x;
    if (i < NG * 128) g_pool[i] = 0.f;
    if (i < NG) g_cnt[i] = 0.f;
}

__global__ void pool_kernel(const void* __restrict__ batch,
                            const float* __restrict__ bias2) {
    int gid  = blockIdx.x * blockDim.x + threadIdx.x;
    int n    = gid >> 5;
    int lane = gid & 31;
    if (n >= Nn) return;
    int g = loadIdx(batch, n);
    float4 v = *(const float4*)(g_out + (size_t)n * 128 + lane * 4);
    const float* bp = bias2 + lane * 4;
    v.x = eluf(v.x + bp[0]);
    v.y = eluf(v.y + bp[1]);
    v.z = eluf(v.z + bp[2]);
    v.w = eluf(v.w + bp[3]);
    red_add_v4(g_pool + g * 128 + lane * 4, v);
    if (lane == 0) atomicAdd(&g_cnt[g], 1.0f);
}

// ---------------- classifier head + softmax ----------------
__global__ void head_kernel(const float* __restrict__ lw,
                            const float* __restrict__ lb,
                            float* __restrict__ out) {
    int g = threadIdx.x;
    if (g >= NG) return;
    float inv = 1.0f / fmaxf(g_cnt[g], 1.0f);
    float lg[NCLS];
#pragma unroll
    for (int c = 0; c < NCLS; c++) lg[c] = lb[c];
    for (int k = 0; k < 128; k++) {
        float pv = g_pool[g * 128 + k] * inv;
#pragma unroll
        for (int c = 0; c < NCLS; c++) lg[c] = fmaf(pv, lw[k * NCLS + c], lg[c]);
    }
    float mx = lg[0];
#pragma unroll
    for (int c = 1; c < NCLS; c++) mx = fmaxf(mx, lg[c]);
    float ssum = 0.f;
#pragma unroll
    for (int c = 0; c < NCLS; c++) { lg[c] = __expf(lg[c] - mx); ssum += lg[c]; }
    float is = 1.0f / ssum;
#pragma unroll
    for (int c = 0; c < NCLS; c++) out[g * NCLS + c] = lg[c] * is;
}

// ---------------- launch ----------------
extern "C" void kernel_launch(void* const* d_in, const int* in_sizes, int n_in,
                              void* d_out, int out_size) {
    const float* x    = (const float*)d_in[0];
    const void*  ei   = d_in[1];
    const void*  bat  = d_in[2];
    const float* W    = (const float*)d_in[3];
    const float* asrc = (const float*)d_in[4];
    const float* adst = (const float*)d_in[5];
    const float* bias = (const float*)d_in[6];
    const float* lw   = (const float*)d_in[7];
    const float* lb   = (const float*)d_in[8];

    const int gemmBlocks     = (Nn + 127) / 128;
    const int nodeWarpBlocks = (Nn * 32 + 255) / 256;
    const int edgeBlocks     = (E2c + 255) / 256;
    const int nodeBlocks     = (Nn + 255) / 256;

    detect_kernel<<<1, 256>>>((const int*)ei);

    // CSR build (once per launch)
    zero_deg_kernel<<<nodeBlocks, 256>>>();
    degree_kernel<<<edgeBlocks, 256>>>(ei);
    scan_kernel<<<1, 1024>>>();
    fill_kernel<<<edgeBlocks, 256>>>(ei);

    for (int l = 0; l < 3; l++) {
        if (l == 0)
            gemm_kernel<0><<<gemmBlocks, 256>>>(x, W, nullptr,
                                                asrc, adst);
        else
            gemm_kernel<1><<<gemmBlocks, 256>>>(nullptr, W + l * 16384,
                                                bias + (l - 1) * 128,
                                                asrc + l * 128, adst + l * 128);
        aggregate_kernel<<<nodeWarpBlocks, 256>>>();
    }
    init_pool_kernel<<<(NG * 128 + 255) / 256, 256>>>();
    pool_kernel<<<nodeWarpBlocks, 256>>>(bat, bias + 2 * 128);
    head_kernel<<<1, 64>>>(lw, lb, (float*)d_out);
}

// round 12
// speedup vs baseline: 1.0092x; 1.0036x over previous
#include <cuda_runtime.h>
#include <math.h>

#define Nn   50000
#define Ee   800000
#define E2c  850000      // E + N self-loops
#define NG   64
#define NCLS 10

// ---------------- device scratch ----------------
__device__ float g_h[(size_t)Nn * 128];     // per-layer GEMM output  [N,128]
__device__ float g_out[(size_t)Nn * 128];   // per-layer aggregation  [N,128] (normalized)
__device__ float g_asrc[Nn * 2];            // alpha_src  [N,H]
__device__ float g_adst[Nn * 2];            // alpha_dst  [N,H]
__device__ int   g_deg[Nn];                 // degree counts
__device__ int   g_rowptr[Nn + 1];          // CSR row offsets
__device__ int   g_cursor[Nn];              // fill cursors
__device__ int   g_eidx[E2c];               // src node per CSR slot
__device__ float g_pool[NG * 128];
__device__ float g_cnt[NG];
__device__ int   g_is64;

// ---------------- helpers ----------------
__device__ __forceinline__ float eluf(float v) { return v > 0.f ? v : expm1f(v); }
__device__ __forceinline__ int loadIdx(const void* p, int i) {
    if (g_is64) return (int)((const long long*)p)[i];
    return ((const int*)p)[i];
}
__device__ __forceinline__ void red_add_v4(float* dst, float4 v) {
    asm volatile("red.global.add.v4.f32 [%0], {%1,%2,%3,%4};"
                 :: "l"(dst), "f"(v.x), "f"(v.y), "f"(v.z), "f"(v.w) : "memory");
}

// ---------------- dtype detection (int32 vs int64 edge indices) ----------------
__global__ void detect_kernel(const int* ei32) {
    __shared__ int sh;
    if (threadIdx.x == 0) sh = 0;
    __syncthreads();
    int v = 0;
    for (int i = threadIdx.x; i < 2048; i += 256) v |= ei32[2 * i + 1];
    atomicOr(&sh, v);
    __syncthreads();
    if (threadIdx.x == 0) g_is64 = (sh == 0) ? 1 : 0;
}

// ---------------- CSR build ----------------
__global__ void zero_deg_kernel() {
    int i = blockIdx.x * blockDim.x + threadIdx.x;
    if (i < Nn) g_deg[i] = 0;
}

__global__ void degree_kernel(const void* __restrict__ ei) {
    int e = blockIdx.x * blockDim.x + threadIdx.x;
    if (e >= E2c) return;
    int d = (e < Ee) ? loadIdx(ei, Ee + e) : (e - Ee);
    atomicAdd(&g_deg[d], 1);
}

__global__ void scan_kernel() {
    __shared__ int sh[1024];
    __shared__ int carry;
    int tid = threadIdx.x;
    if (tid == 0) carry = 0;
    __syncthreads();
    for (int chunk = 0; chunk < Nn; chunk += 1024) {
        int idx = chunk + tid;
        int v = (idx < Nn) ? g_deg[idx] : 0;
        sh[tid] = v;
        __syncthreads();
        for (int o = 1; o < 1024; o <<= 1) {
            int t = (tid >= o) ? sh[tid - o] : 0;
            __syncthreads();
            sh[tid] += t;
            __syncthreads();
        }
        int excl = carry + sh[tid] - v;
        if (idx < Nn) { g_rowptr[idx] = excl; g_cursor[idx] = excl; }
        __syncthreads();
        if (tid == 0) carry += sh[1023];
        __syncthreads();
    }
    if (tid == 0) g_rowptr[Nn] = carry;
}

__global__ void fill_kernel(const void* __restrict__ ei) {
    int e = blockIdx.x * blockDim.x + threadIdx.x;
    if (e >= E2c) return;
    int s, d;
    if (e < Ee) { s = loadIdx(ei, e); d = loadIdx(ei, Ee + e); }
    else        { s = e - Ee; d = s; }
    int pos = atomicAdd(&g_cursor[d], 1);
    g_eidx[pos] = s;
}

// ---------------- GEMM + fused alpha epilogue ----------------
// MODE 0: X = raw input. MODE 1: X = elu(g_out + biasPrev) (g_out pre-normalized)
template <int MODE>
__global__ void gemm_kernel(const float* __restrict__ X,
                            const float* __restrict__ Wm,
                            const float* __restrict__ biasPrev,
                            const float* __restrict__ attS,
                            const float* __restrict__ attD) {
    __shared__ float As[16][128];   // [k][m]
    __shared__ float Bs[16][128];   // [k][n]
    const int tid = threadIdx.x;
    const int bm  = blockIdx.x * 128;
    const int tx  = tid & 15;
    const int ty  = tid >> 4;
    float acc[8][8];
#pragma unroll
    for (int i = 0; i < 8; i++)
#pragma unroll
        for (int j = 0; j < 8; j++) acc[i][j] = 0.f;

    for (int k0 = 0; k0 < 128; k0 += 16) {
#pragma unroll
        for (int t = 0; t < 2; t++) {
            int e   = tid + t * 256;
            int row = e >> 2;
            int kk4 = (e & 3) << 2;
            int gr  = bm + row;
            float4 v = make_float4(0.f, 0.f, 0.f, 0.f);
            if (gr < Nn) {
                if (MODE == 0) {
                    v = *(const float4*)(X + (size_t)gr * 128 + k0 + kk4);
                } else {
                    v = *(const float4*)(g_out + (size_t)gr * 128 + k0 + kk4);
                    v.x = eluf(v.x + biasPrev[k0 + kk4 + 0]);
                    v.y = eluf(v.y + biasPrev[k0 + kk4 + 1]);
                    v.z = eluf(v.z + biasPrev[k0 + kk4 + 2]);
                    v.w = eluf(v.w + biasPrev[k0 + kk4 + 3]);
                }
            }
            As[kk4 + 0][row] = v.x;
            As[kk4 + 1][row] = v.y;
            As[kk4 + 2][row] = v.z;
            As[kk4 + 3][row] = v.w;
            int kb = e >> 5;
            int n4 = (e & 31) << 2;
            *(float4*)&Bs[kb][n4] = *(const float4*)(Wm + (size_t)(k0 + kb) * 128 + n4);
        }
        __syncthreads();
#pragma unroll
        for (int kk = 0; kk < 16; kk++) {
            float a[8], b[8];
            *(float4*)&a[0] = *(const float4*)&As[kk][ty * 8];
            *(float4*)&a[4] = *(const float4*)&As[kk][ty * 8 + 4];
            *(float4*)&b[0] = *(const float4*)&Bs[kk][tx * 8];
            *(float4*)&b[4] = *(const float4*)&Bs[kk][tx * 8 + 4];
#pragma unroll
            for (int i = 0; i < 8; i++)
#pragma unroll
                for (int j = 0; j < 8; j++)
                    acc[i][j] = fmaf(a[i], b[j], acc[i][j]);
        }
        __syncthreads();
    }

    // store h
#pragma unroll
    for (int i = 0; i < 8; i++) {
        int gr = bm + ty * 8 + i;
        if (gr < Nn) {
            *(float4*)(g_h + (size_t)gr * 128 + tx * 8) =
                make_float4(acc[i][0], acc[i][1], acc[i][2], acc[i][3]);
            *(float4*)(g_h + (size_t)gr * 128 + tx * 8 + 4) =
                make_float4(acc[i][4], acc[i][5], acc[i][6], acc[i][7]);
        }
    }

    // fused alpha: this thread's 8 cols (tx*8..tx*8+7) lie in one head (tx<8 -> head0)
    float as[8], ad[8];
    *(float4*)&as[0] = *(const float4*)(attS + tx * 8);
    *(float4*)&as[4] = *(const float4*)(attS + tx * 8 + 4);
    *(float4*)&ad[0] = *(const float4*)(attD + tx * 8);
    *(float4*)&ad[4] = *(const float4*)(attD + tx * 8 + 4);
    int head = tx >> 3;
#pragma unroll
    for (int i = 0; i < 8; i++) {
        float s = 0.f, d = 0.f;
#pragma unroll
        for (int j = 0; j < 8; j++) {
            s = fmaf(acc[i][j], as[j], s);
            d = fmaf(acc[i][j], ad[j], d);
        }
#pragma unroll
        for (int o = 4; o; o >>= 1) {
            s += __shfl_xor_sync(0xFFFFFFFFu, s, o);
            d += __shfl_xor_sync(0xFFFFFFFFu, d, o);
        }
        if ((tx & 7) == 0) {
            int gr = bm + ty * 8 + i;
            if (gr < Nn) {
                g_asrc[gr * 2 + head] = s;
                g_adst[gr * 2 + head] = d;
            }
        }
    }
}

// ---------------- fused edge softmax + aggregate (warp per dst node) ----------------
__global__ void aggregate_kernel() {
    int gid  = blockIdx.x * blockDim.x + threadIdx.x;
    int n    = gid >> 5;
    if (n >= Nn) return;
    int lane = gid & 31;
    int hh   = lane >> 4;

    float ad0 = g_adst[n * 2 + 0];
    float ad1 = g_adst[n * 2 + 1];
    int start = g_rowptr[n];
    int end   = g_rowptr[n + 1];

    float z0 = 0.f, z1 = 0.f;
    float4 accA = make_float4(0.f, 0.f, 0.f, 0.f);
    float4 accB = make_float4(0.f, 0.f, 0.f, 0.f);

    for (int base = start; base < end; base += 32) {
        int i = base + lane;
        int s = 0; float p0 = 0.f, p1 = 0.f;
        if (i < end) {
            s = g_eidx[i];
            float l0 = g_asrc[s * 2 + 0] + ad0; l0 = l0 > 0.f ? l0 : 0.2f * l0;
            float l1 = g_asrc[s * 2 + 1] + ad1; l1 = l1 > 0.f ? l1 : 0.2f * l1;
            p0 = __expf(l0); p1 = __expf(l1);
            z0 += p0; z1 += p1;
        }
        int cnt = min(32, end - base);
        int j = 0;
        for (; j + 1 < cnt; j += 2) {
            int   sA  = __shfl_sync(0xFFFFFFFFu, s, j);
            float pA0 = __shfl_sync(0xFFFFFFFFu, p0, j);
            float pA1 = __shfl_sync(0xFFFFFFFFu, p1, j);
            int   sB  = __shfl_sync(0xFFFFFFFFu, s, j + 1);
            float pB0 = __shfl_sync(0xFFFFFFFFu, p0, j + 1);
            float pB1 = __shfl_sync(0xFFFFFFFFu, p1, j + 1);
            float pA = hh ? pA1 : pA0;
            float pB = hh ? pB1 : pB0;
            float4 hA = *(const float4*)(g_h + (size_t)sA * 128 + lane * 4);
            float4 hB = *(const float4*)(g_h + (size_t)sB * 128 + lane * 4);
            accA.x = fmaf(pA, hA.x, accA.x); accA.y = fmaf(pA, hA.y, accA.y);
            accA.z = fmaf(pA, hA.z, accA.z); accA.w = fmaf(pA, hA.w, accA.w);
            accB.x = fmaf(pB, hB.x, accB.x); accB.y = fmaf(pB, hB.y, accB.y);
            accB.z = fmaf(pB, hB.z, accB.z); accB.w = fmaf(pB, hB.w, accB.w);
        }
        if (j < cnt) {
            int   sA  = __shfl_sync(0xFFFFFFFFu, s, j);
            float pA0 = __shfl_sync(0xFFFFFFFFu, p0, j);
            float pA1 = __shfl_sync(0xFFFFFFFFu, p1, j);
            float pA = hh ? pA1 : pA0;
            float4 hA = *(const float4*)(g_h + (size_t)sA * 128 + lane * 4);
            accA.x = fmaf(pA, hA.x, accA.x); accA.y = fmaf(pA, hA.y, accA.y);
            accA.z = fmaf(pA, hA.z, accA.z); accA.w = fmaf(pA, hA.w, accA.w);
        }
    }
#pragma unroll
    for (int o = 16; o; o >>= 1) {
        z0 += __shfl_xor_sync(0xFFFFFFFFu, z0, o);
        z1 += __shfl_xor_sync(0xFFFFFFFFu, z1, o);
    }
    float inv = 1.0f / (hh ? z1 : z0);
    float4 r;
    r.x = (accA.x + accB.x) * inv;
    r.y = (accA.y + accB.y) * inv;
    r.z = (accA.z + accB.z) * inv;
    r.w = (accA.w + accB.w) * inv;
    *(float4*)(g_out + (size_t)n * 128 + lane * 4) = r;
}

// ---------------- pooling ----------------
__global__ void init_pool_kernel() {
    int i = blockIdx.x * blockDim.x + threadIdx.x;
    if (i < NG * 128) g_pool[i] = 0.f;
    if (i < NG) g_cnt[i] = 0.f;
}

__global__ void pool_kernel(const void* __restrict__ batch,
                            const float* __restrict__ bias2) {
    int gid  = blockIdx.x * blockDim.x + threadIdx.x;
    int n    = gid >> 5;
    int lane = gid & 31;
    if (n >= Nn) return;
    int g = loadIdx(batch, n);
    float4 v = *(const float4*)(g_out + (size_t)n * 128 + lane * 4);
    const float* bp = bias2 + lane * 4;
    v.x = eluf(v.x + bp[0]);
    v.y = eluf(v.y + bp[1]);
    v.z = eluf(v.z + bp[2]);
    v.w = eluf(v.w + bp[3]);
    red_add_v4(g_pool + g * 128 + lane * 4, v);
    if (lane == 0) atomicAdd(&g_cnt[g], 1.0f);
}

// ---------------- classifier head + softmax ----------------
__global__ void head_kernel(const float* __restrict__ lw,
                            const float* __restrict__ lb,
                            float* __restrict__ out) {
    int g = threadIdx.x;
    if (g >= NG) return;
    float inv = 1.0f / fmaxf(g_cnt[g], 1.0f);
    float lg[NCLS];
#pragma unroll
    for (int c = 0; c < NCLS; c++) lg[c] = lb[c];
    for (int k = 0; k < 128; k++) {
        float pv = g_pool[g * 128 + k] * inv;
#pragma unroll
        for (int c = 0; c < NCLS; c++) lg[c] = fmaf(pv, lw[k * NCLS + c], lg[c]);
    }
    float mx = lg[0];
#pragma unroll
    for (int c = 1; c < NCLS; c++) mx = fmaxf(mx, lg[c]);
    float ssum = 0.f;
#pragma unroll
    for (int c = 0; c < NCLS; c++) { lg[c] = __expf(lg[c] - mx); ssum += lg[c]; }
    float is = 1.0f / ssum;
#pragma unroll
    for (int c = 0; c < NCLS; c++) out[g * NCLS + c] = lg[c] * is;
}

// ---------------- launch ----------------
extern "C" void kernel_launch(void* const* d_in, const int* in_sizes, int n_in,
                              void* d_out, int out_size) {
    const float* x    = (const float*)d_in[0];
    const void*  ei   = d_in[1];
    const void*  bat  = d_in[2];
    const float* W    = (const float*)d_in[3];
    const float* asrc = (const float*)d_in[4];
    const float* adst = (const float*)d_in[5];
    const float* bias = (const float*)d_in[6];
    const float* lw   = (const float*)d_in[7];
    const float* lb   = (const float*)d_in[8];

    const int gemmBlocks     = (Nn + 127) / 128;
    const int nodeWarpBlocks = (Nn * 32 + 255) / 256;
    const int edgeBlocks     = (E2c + 255) / 256;
    const int nodeBlocks     = (Nn + 255) / 256;

    detect_kernel<<<1, 256>>>((const int*)ei);

    // CSR build (once per launch)
    zero_deg_kernel<<<nodeBlocks, 256>>>();
    degree_kernel<<<edgeBlocks, 256>>>(ei);
    scan_kernel<<<1, 1024>>>();
    fill_kernel<<<edgeBlocks, 256>>>(ei);

    for (int l = 0; l < 3; l++) {
        if (l == 0)
            gemm_kernel<0><<<gemmBlocks, 256>>>(x, W, nullptr,
                                                asrc, adst);
        else
            gemm_kernel<1><<<gemmBlocks, 256>>>(nullptr, W + l * 16384,
                                                bias + (l - 1) * 128,
                                                asrc + l * 128, adst + l * 128);
        aggregate_kernel<<<nodeWarpBlocks, 256>>>();
    }
    init_pool_kernel<<<(NG * 128 + 255) / 256, 256>>>();
    pool_kernel<<<nodeWarpBlocks, 256>>>(bat, bias + 2 * 128);
    head_kernel<<<1, 64>>>(lw, lb, (float*)d_out);
}

// round 13
// speedup vs baseline: 1.0178x; 1.0086x over previous
#include <cuda_runtime.h>
#include <math.h>

#define Nn   50000
#define Ee   800000
#define E2c  850000      // E + N self-loops
#define NG   64
#define NCLS 10

// ---------------- device scratch ----------------
__device__ float g_h[(size_t)Nn * 128];     // per-layer GEMM output  [N,128]
__device__ float g_out[(size_t)Nn * 128];   // per-layer aggregation  [N,128] (normalized)
__device__ float g_asrc[Nn * 2];            // alpha_src  [N,H]
__device__ float g_adst[Nn * 2];            // alpha_dst  [N,H]
__device__ int   g_deg[Nn];                 // degree counts
__device__ int   g_rowptr[Nn + 1];          // CSR row offsets
__device__ int   g_cursor[Nn];              // fill cursors
__device__ int   g_eidx[E2c];               // src node per CSR slot
__device__ float g_pool[NG * 128];
__device__ float g_cnt[NG];
__device__ int   g_is64;

// ---------------- helpers ----------------
__device__ __forceinline__ float eluf(float v) { return v > 0.f ? v : expm1f(v); }
__device__ __forceinline__ int loadIdx(const void* p, int i) {
    if (g_is64) return (int)((const long long*)p)[i];
    return ((const int*)p)[i];
}
__device__ __forceinline__ void red_add_v4(float* dst, float4 v) {
    asm volatile("red.global.add.v4.f32 [%0], {%1,%2,%3,%4};"
                 :: "l"(dst), "f"(v.x), "f"(v.y), "f"(v.z), "f"(v.w) : "memory");
}

// ---------------- dtype detection (int32 vs int64 edge indices) ----------------
__global__ void detect_kernel(const int* ei32) {
    __shared__ int sh;
    if (threadIdx.x == 0) sh = 0;
    __syncthreads();
    int v = 0;
    for (int i = threadIdx.x; i < 2048; i += 256) v |= ei32[2 * i + 1];
    atomicOr(&sh, v);
    __syncthreads();
    if (threadIdx.x == 0) g_is64 = (sh == 0) ? 1 : 0;
}

// ---------------- CSR build ----------------
__global__ void zero_deg_kernel() {
    int i = blockIdx.x * blockDim.x + threadIdx.x;
    if (i < Nn) g_deg[i] = 0;
}

__global__ void degree_kernel(const void* __restrict__ ei) {
    int e = blockIdx.x * blockDim.x + threadIdx.x;
    if (e >= E2c) return;
    int d = (e < Ee) ? loadIdx(ei, Ee + e) : (e - Ee);
    atomicAdd(&g_deg[d], 1);
}

__global__ void scan_kernel() {
    __shared__ int sh[1024];
    __shared__ int carry;
    int tid = threadIdx.x;
    if (tid == 0) carry = 0;
    __syncthreads();
    for (int chunk = 0; chunk < Nn; chunk += 1024) {
        int idx = chunk + tid;
        int v = (idx < Nn) ? g_deg[idx] : 0;
        sh[tid] = v;
        __syncthreads();
        for (int o = 1; o < 1024; o <<= 1) {
            int t = (tid >= o) ? sh[tid - o] : 0;
            __syncthreads();
            sh[tid] += t;
            __syncthreads();
        }
        int excl = carry + sh[tid] - v;
        if (idx < Nn) { g_rowptr[idx] = excl; g_cursor[idx] = excl; }
        __syncthreads();
        if (tid == 0) carry += sh[1023];
        __syncthreads();
    }
    if (tid == 0) g_rowptr[Nn] = carry;
}

__global__ void fill_kernel(const void* __restrict__ ei) {
    int e = blockIdx.x * blockDim.x + threadIdx.x;
    if (e >= E2c) return;
    int s, d;
    if (e < Ee) { s = loadIdx(ei, e); d = loadIdx(ei, Ee + e); }
    else        { s = e - Ee; d = s; }
    int pos = atomicAdd(&g_cursor[d], 1);
    g_eidx[pos] = s;
}

// ---------------- GEMM + fused alpha epilogue ----------------
// MODE 0: X = raw input. MODE 1: X = elu(g_out + biasPrev) (g_out pre-normalized)
template <int MODE>
__global__ void gemm_kernel(const float* __restrict__ X,
                            const float* __restrict__ Wm,
                            const float* __restrict__ biasPrev,
                            const float* __restrict__ attS,
                            const float* __restrict__ attD) {
    __shared__ float As[16][128];   // [k][m]
    __shared__ float Bs[16][128];   // [k][n]
    const int tid = threadIdx.x;
    const int bm  = blockIdx.x * 128;
    const int tx  = tid & 15;
    const int ty  = tid >> 4;
    float acc[8][8];
#pragma unroll
    for (int i = 0; i < 8; i++)
#pragma unroll
        for (int j = 0; j < 8; j++) acc[i][j] = 0.f;

    for (int k0 = 0; k0 < 128; k0 += 16) {
#pragma unroll
        for (int t = 0; t < 2; t++) {
            int e   = tid + t * 256;
            int row = e >> 2;
            int kk4 = (e & 3) << 2;
            int gr  = bm + row;
            float4 v = make_float4(0.f, 0.f, 0.f, 0.f);
            if (gr < Nn) {
                if (MODE == 0) {
                    v = *(const float4*)(X + (size_t)gr * 128 + k0 + kk4);
                } else {
                    v = *(const float4*)(g_out + (size_t)gr * 128 + k0 + kk4);
                    v.x = eluf(v.x + biasPrev[k0 + kk4 + 0]);
                    v.y = eluf(v.y + biasPrev[k0 + kk4 + 1]);
                    v.z = eluf(v.z + biasPrev[k0 + kk4 + 2]);
                    v.w = eluf(v.w + biasPrev[k0 + kk4 + 3]);
                }
            }
            As[kk4 + 0][row] = v.x;
            As[kk4 + 1][row] = v.y;
            As[kk4 + 2][row] = v.z;
            As[kk4 + 3][row] = v.w;
            int kb = e >> 5;
            int n4 = (e & 31) << 2;
            *(float4*)&Bs[kb][n4] = *(const float4*)(Wm + (size_t)(k0 + kb) * 128 + n4);
        }
        __syncthreads();
#pragma unroll
        for (int kk = 0; kk < 16; kk++) {
            float a[8], b[8];
            *(float4*)&a[0] = *(const float4*)&As[kk][ty * 8];
            *(float4*)&a[4] = *(const float4*)&As[kk][ty * 8 + 4];
            *(float4*)&b[0] = *(const float4*)&Bs[kk][tx * 8];
            *(float4*)&b[4] = *(const float4*)&Bs[kk][tx * 8 + 4];
#pragma unroll
            for (int i = 0; i < 8; i++)
#pragma unroll
                for (int j = 0; j < 8; j++)
                    acc[i][j] = fmaf(a[i], b[j], acc[i][j]);
        }
        __syncthreads();
    }

    // store h
#pragma unroll
    for (int i = 0; i < 8; i++) {
        int gr = bm + ty * 8 + i;
        if (gr < Nn) {
            *(float4*)(g_h + (size_t)gr * 128 + tx * 8) =
                make_float4(acc[i][0], acc[i][1], acc[i][2], acc[i][3]);
            *(float4*)(g_h + (size_t)gr * 128 + tx * 8 + 4) =
                make_float4(acc[i][4], acc[i][5], acc[i][6], acc[i][7]);
        }
    }

    // fused alpha: this thread's 8 cols (tx*8..tx*8+7) lie in one head (tx<8 -> head0)
    float as[8], ad[8];
    *(float4*)&as[0] = *(const float4*)(attS + tx * 8);
    *(float4*)&as[4] = *(const float4*)(attS + tx * 8 + 4);
    *(float4*)&ad[0] = *(const float4*)(attD + tx * 8);
    *(float4*)&ad[4] = *(const float4*)(attD + tx * 8 + 4);
    int head = tx >> 3;
#pragma unroll
    for (int i = 0; i < 8; i++) {
        float s = 0.f, d = 0.f;
#pragma unroll
        for (int j = 0; j < 8; j++) {
            s = fmaf(acc[i][j], as[j], s);
            d = fmaf(acc[i][j], ad[j], d);
        }
#pragma unroll
        for (int o = 4; o; o >>= 1) {
            s += __shfl_xor_sync(0xFFFFFFFFu, s, o);
            d += __shfl_xor_sync(0xFFFFFFFFu, d, o);
        }
        if ((tx & 7) == 0) {
            int gr = bm + ty * 8 + i;
            if (gr < Nn) {
                g_asrc[gr * 2 + head] = s;
                g_adst[gr * 2 + head] = d;
            }
        }
    }
}

// ---------------- fused edge softmax + aggregate (warp per dst node) ----------------
__global__ void aggregate_kernel() {
    int gid  = blockIdx.x * blockDim.x + threadIdx.x;
    int n    = gid >> 5;
    if (n >= Nn) return;
    int lane = gid & 31;
    int hh   = lane >> 4;

    float ad0 = g_adst[n * 2 + 0];
    float ad1 = g_adst[n * 2 + 1];
    int start = g_rowptr[n];
    int end   = g_rowptr[n + 1];

    float z0 = 0.f, z1 = 0.f;
    float4 accA = make_float4(0.f, 0.f, 0.f, 0.f);
    float4 accB = make_float4(0.f, 0.f, 0.f, 0.f);

    for (int base = start; base < end; base += 32) {
        int i = base + lane;
        int s = 0; float p0 = 0.f, p1 = 0.f;
        if (i < end) {
            s = g_eidx[i];
            float l0 = g_asrc[s * 2 + 0] + ad0; l0 = l0 > 0.f ? l0 : 0.2f * l0;
            float l1 = g_asrc[s * 2 + 1] + ad1; l1 = l1 > 0.f ? l1 : 0.2f * l1;
            p0 = __expf(l0); p1 = __expf(l1);
            z0 += p0; z1 += p1;
        }
        int cnt = min(32, end - base);
        int j = 0;
        for (; j + 1 < cnt; j += 2) {
            int   sA  = __shfl_sync(0xFFFFFFFFu, s, j);
            float pA0 = __shfl_sync(0xFFFFFFFFu, p0, j);
            float pA1 = __shfl_sync(0xFFFFFFFFu, p1, j);
            int   sB  = __shfl_sync(0xFFFFFFFFu, s, j + 1);
            float pB0 = __shfl_sync(0xFFFFFFFFu, p0, j + 1);
            float pB1 = __shfl_sync(0xFFFFFFFFu, p1, j + 1);
            float pA = hh ? pA1 : pA0;
            float pB = hh ? pB1 : pB0;
            float4 hA = *(const float4*)(g_h + (size_t)sA * 128 + lane * 4);
            float4 hB = *(const float4*)(g_h + (size_t)sB * 128 + lane * 4);
            accA.x = fmaf(pA, hA.x, accA.x); accA.y = fmaf(pA, hA.y, accA.y);
            accA.z = fmaf(pA, hA.z, accA.z); accA.w = fmaf(pA, hA.w, accA.w);
            accB.x = fmaf(pB, hB.x, accB.x); accB.y = fmaf(pB, hB.y, accB.y);
            accB.z = fmaf(pB, hB.z, accB.z); accB.w = fmaf(pB, hB.w, accB.w);
        }
        if (j < cnt) {
            int   sA  = __shfl_sync(0xFFFFFFFFu, s, j);
            float pA0 = __shfl_sync(0xFFFFFFFFu, p0, j);
            float pA1 = __shfl_sync(0xFFFFFFFFu, p1, j);
            float pA = hh ? pA1 : pA0;
            float4 hA = *(const float4*)(g_h + (size_t)sA * 128 + lane * 4);
            accA.x = fmaf(pA, hA.x, accA.x); accA.y = fmaf(pA, hA.y, accA.y);
            accA.z = fmaf(pA, hA.z, accA.z); accA.w = fmaf(pA, hA.w, accA.w);
        }
    }
#pragma unroll
    for (int o = 16; o; o >>= 1) {
        z0 += __shfl_xor_sync(0xFFFFFFFFu, z0, o);
        z1 += __shfl_xor_sync(0xFFFFFFFFu, z1, o);
    }
    float inv = 1.0f / (hh ? z1 : z0);
    float4 r;
    r.x = (accA.x + accB.x) * inv;
    r.y = (accA.y + accB.y) * inv;
    r.z = (accA.z + accB.z) * inv;
    r.w = (accA.w + accB.w) * inv;
    *(float4*)(g_out + (size_t)n * 128 + lane * 4) = r;
}

// ---------------- pooling ----------------
__global__ void init_pool_kernel() {
    int i = blockIdx.x * blockDim.x + threadIdx.x;
    if (i < NG * 128) g_pool[i] = 0.f;
    if (i < NG) g_cnt[i] = 0.f;
}

__global__ void pool_kernel(const void* __restrict__ batch,
                            const float* __restrict__ bias2) {
    int gid  = blockIdx.x * blockDim.x + threadIdx.x;
    int n    = gid >> 5;
    int lane = gid & 31;
    if (n >= Nn) return;
    int g = loadIdx(batch, n);
    float4 v = *(const float4*)(g_out + (size_t)n * 128 + lane * 4);
    const float* bp = bias2 + lane * 4;
    v.x = eluf(v.x + bp[0]);
    v.y = eluf(v.y + bp[1]);
    v.z = eluf(v.z + bp[2]);
    v.w = eluf(v.w + bp[3]);
    red_add_v4(g_pool + g * 128 + lane * 4, v);
    if (lane == 0) atomicAdd(&g_cnt[g], 1.0f);
}

// ---------------- classifier head + softmax ----------------
__global__ void head_kernel(const float* __restrict__ lw,
                            const float* __restrict__ lb,
                            float* __restrict__ out) {
    int g = threadIdx.x;
    if (g >= NG) return;
    float inv = 1.0f / fmaxf(g_cnt[g], 1.0f);
    float lg[NCLS];
#pragma unroll
    for (int c = 0; c < NCLS; c++) lg[c] = lb[c];
    for (int k = 0; k < 128; k++) {
        float pv = g_pool[g * 128 + k] * inv;
#pragma unroll
        for (int c = 0; c < NCLS; c++) lg[c] = fmaf(pv, lw[k * NCLS + c], lg[c]);
    }
    float mx = lg[0];
#pragma unroll
    for (int c = 1; c < NCLS; c++) mx = fmaxf(mx, lg[c]);
    float ssum = 0.f;
#pragma unroll
    for (int c = 0; c < NCLS; c++) { lg[c] = __expf(lg[c] - mx); ssum += lg[c]; }
    float is = 1.0f / ssum;
#pragma unroll
    for (int c = 0; c < NCLS; c++) out[g * NCLS + c] = lg[c] * is;
}

// ---------------- launch ----------------
extern "C" void kernel_launch(void* const* d_in, const int* in_sizes, int n_in,
                              void* d_out, int out_size) {
    const float* x    = (const float*)d_in[0];
    const void*  ei   = d_in[1];
    const void*  bat  = d_in[2];
    const float* W    = (const float*)d_in[3];
    const float* asrc = (const float*)d_in[4];
    const float* adst = (const float*)d_in[5];
    const float* bias = (const float*)d_in[6];
    const float* lw   = (const float*)d_in[7];
    const float* lb   = (const float*)d_in[8];

    const int gemmBlocks     = (Nn + 127) / 128;
    const int nodeWarpBlocks = (Nn * 32 + 255) / 256;
    const int edgeBlocks     = (E2c + 255) / 256;
    const int nodeBlocks     = (Nn + 255) / 256;

    detect_kernel<<<1, 256>>>((const int*)ei);

    // CSR build (once per launch)
    zero_deg_kernel<<<nodeBlocks, 256>>>();
    degree_kernel<<<edgeBlocks, 256>>>(ei);
    scan_kernel<<<1, 1024>>>();
    fill_kernel<<<edgeBlocks, 256>>>(ei);

    for (int l = 0; l < 3; l++) {
        if (l == 0)
            gemm_kernel<0><<<gemmBlocks, 256>>>(x, W, nullptr,
                                                asrc, adst);
        else
            gemm_kernel<1><<<gemmBlocks, 256>>>(nullptr, W + l * 16384,
                                                bias + (l - 1) * 128,
                                                asrc + l * 128, adst + l * 128);
        aggregate_kernel<<<nodeWarpBlocks, 256>>>();
    }
    init_pool_kernel<<<(NG * 128 + 255) / 256, 256>>>();
    pool_kernel<<<nodeWarpBlocks, 256>>>(bat, bias + 2 * 128);
    head_kernel<<<1, 64>>>(lw, lb, (float*)d_out);
}

// round 14
// speedup vs baseline: 1.1482x; 1.1281x over previous
#include <cuda_runtime.h>
#include <math.h>

#define Nn   50000
#define Ee   800000
#define E2c  850000      // E + N self-loops
#define NG   64
#define NCLS 10

#define SCAN_BLK 1024
#define NSCANB ((Nn + SCAN_BLK - 1) / SCAN_BLK)   // 49

// ---------------- device scratch ----------------
__device__ float g_h[(size_t)Nn * 128];     // per-layer GEMM output  [N,128]
__device__ float g_out[(size_t)Nn * 128];   // per-layer aggregation  [N,128] (normalized)
__device__ float g_asrc[Nn * 2];            // alpha_src  [N,H]
__device__ float g_adst[Nn * 2];            // alpha_dst  [N,H]
__device__ int   g_deg[Nn];                 // degree counts
__device__ int   g_rowptr[Nn + 1];          // CSR row offsets
__device__ int   g_cursor[Nn];              // fill cursors
__device__ int   g_eidx[E2c];               // src node per CSR slot
__device__ int   g_bsum[NSCANB];            // per-block scan totals
__device__ int   g_boff[NSCANB];            // per-block exclusive offsets
__device__ float g_pool[NG * 128];
__device__ float g_cnt[NG];
__device__ int   g_is64;

// ---------------- helpers ----------------
__device__ __forceinline__ float eluf(float v) { return v > 0.f ? v : expm1f(v); }
__device__ __forceinline__ int loadIdx(const void* p, int i) {
    if (g_is64) return (int)((const long long*)p)[i];
    return ((const int*)p)[i];
}
__device__ __forceinline__ void red_add_v4(float* dst, float4 v) {
    asm volatile("red.global.add.v4.f32 [%0], {%1,%2,%3,%4};"
                 :: "l"(dst), "f"(v.x), "f"(v.y), "f"(v.z), "f"(v.w) : "memory");
}

// ---------------- dtype detection (int32 vs int64 edge indices) ----------------
__global__ void detect_kernel(const int* ei32) {
    __shared__ int sh;
    if (threadIdx.x == 0) sh = 0;
    __syncthreads();
    int v = 0;
    for (int i = threadIdx.x; i < 2048; i += 256) v |= ei32[2 * i + 1];
    atomicOr(&sh, v);
    __syncthreads();
    if (threadIdx.x == 0) g_is64 = (sh == 0) ? 1 : 0;
}

// ---------------- CSR build ----------------
__global__ void zero_deg_kernel() {
    int i = blockIdx.x * blockDim.x + threadIdx.x;
    if (i < Nn) g_deg[i] = 0;
}

__global__ void degree_kernel(const void* __restrict__ ei) {
    int e = blockIdx.x * blockDim.x + threadIdx.x;
    if (e >= E2c) return;
    int d = (e < Ee) ? loadIdx(ei, Ee + e) : (e - Ee);
    atomicAdd(&g_deg[d], 1);
}

// multi-block scan, phase 1: per-block inclusive scan via shuffles
__global__ void scan1_kernel() {
    __shared__ int warpsums[32];
    int tid  = threadIdx.x;
    int lane = tid & 31;
    int wid  = tid >> 5;
    int idx  = blockIdx.x * SCAN_BLK + tid;
    int v = (idx < Nn) ? g_deg[idx] : 0;
    int s = v;
#pragma unroll
    for (int o = 1; o < 32; o <<= 1) {
        int t = __shfl_up_sync(0xFFFFFFFFu, s, o);
        if (lane >= o) s += t;
    }
    if (lane == 31) warpsums[wid] = s;
    __syncthreads();
    if (wid == 0) {
        int ws = warpsums[lane];
#pragma unroll
        for (int o = 1; o < 32; o <<= 1) {
            int t = __shfl_up_sync(0xFFFFFFFFu, ws, o);
            if (lane >= o) ws += t;
        }
        warpsums[lane] = ws;
    }
    __syncthreads();
    int excl = s - v + (wid ? warpsums[wid - 1] : 0);
    if (idx < Nn) g_rowptr[idx] = excl;             // block-local; offset added in phase 3
    if (tid == SCAN_BLK - 1) g_bsum[blockIdx.x] = excl + v;
}

// phase 2: scan the 49 block totals (single thread; unrolled independent loads)
__global__ void scan2_kernel() {
    if (threadIdx.x == 0) {
        int acc = 0;
#pragma unroll
        for (int i = 0; i < NSCANB; i++) {
            g_boff[i] = acc;
            acc += g_bsum[i];
        }
        g_rowptr[Nn] = acc;
    }
}

// phase 3: add block offsets, init cursors
__global__ void scan3_kernel() {
    int idx = blockIdx.x * blockDim.x + threadIdx.x;
    if (idx < Nn) {
        int r = g_rowptr[idx] + g_boff[idx >> 10];
        g_rowptr[idx] = r;
        g_cursor[idx] = r;
    }
}

__global__ void fill_kernel(const void* __restrict__ ei) {
    int e = blockIdx.x * blockDim.x + threadIdx.x;
    if (e >= E2c) return;
    int s, d;
    if (e < Ee) { s = loadIdx(ei, e); d = loadIdx(ei, Ee + e); }
    else        { s = e - Ee; d = s; }
    int pos = atomicAdd(&g_cursor[d], 1);
    g_eidx[pos] = s;
}

// ---------------- GEMM + fused alpha epilogue ----------------
// MODE 0: X = raw input. MODE 1: X = elu(g_out + biasPrev) (g_out pre-normalized)
template <int MODE>
__global__ void gemm_kernel(const float* __restrict__ X,
                            const float* __restrict__ Wm,
                            const float* __restrict__ biasPrev,
                            const float* __restrict__ attS,
                            const float* __restrict__ attD) {
    __shared__ float As[16][128];   // [k][m]
    __shared__ float Bs[16][128];   // [k][n]
    const int tid = threadIdx.x;
    const int bm  = blockIdx.x * 128;
    const int tx  = tid & 15;
    const int ty  = tid >> 4;
    float acc[8][8];
#pragma unroll
    for (int i = 0; i < 8; i++)
#pragma unroll
        for (int j = 0; j < 8; j++) acc[i][j] = 0.f;

    for (int k0 = 0; k0 < 128; k0 += 16) {
#pragma unroll
        for (int t = 0; t < 2; t++) {
            int e   = tid + t * 256;
            int row = e >> 2;
            int kk4 = (e & 3) << 2;
            int gr  = bm + row;
            float4 v = make_float4(0.f, 0.f, 0.f, 0.f);
            if (gr < Nn) {
                if (MODE == 0) {
                    v = *(const float4*)(X + (size_t)gr * 128 + k0 + kk4);
                } else {
                    v = *(const float4*)(g_out + (size_t)gr * 128 + k0 + kk4);
                    v.x = eluf(v.x + biasPrev[k0 + kk4 + 0]);
                    v.y = eluf(v.y + biasPrev[k0 + kk4 + 1]);
                    v.z = eluf(v.z + biasPrev[k0 + kk4 + 2]);
                    v.w = eluf(v.w + biasPrev[k0 + kk4 + 3]);
                }
            }
            As[kk4 + 0][row] = v.x;
            As[kk4 + 1][row] = v.y;
            As[kk4 + 2][row] = v.z;
            As[kk4 + 3][row] = v.w;
            int kb = e >> 5;
            int n4 = (e & 31) << 2;
            *(float4*)&Bs[kb][n4] = *(const float4*)(Wm + (size_t)(k0 + kb) * 128 + n4);
        }
        __syncthreads();
#pragma unroll
        for (int kk = 0; kk < 16; kk++) {
            float a[8], b[8];
            *(float4*)&a[0] = *(const float4*)&As[kk][ty * 8];
            *(float4*)&a[4] = *(const float4*)&As[kk][ty * 8 + 4];
            *(float4*)&b[0] = *(const float4*)&Bs[kk][tx * 8];
            *(float4*)&b[4] = *(const float4*)&Bs[kk][tx * 8 + 4];
#pragma unroll
            for (int i = 0; i < 8; i++)
#pragma unroll
                for (int j = 0; j < 8; j++)
                    acc[i][j] = fmaf(a[i], b[j], acc[i][j]);
        }
        __syncthreads();
    }

    // store h
#pragma unroll
    for (int i = 0; i < 8; i++) {
        int gr = bm + ty * 8 + i;
        if (gr < Nn) {
            *(float4*)(g_h + (size_t)gr * 128 + tx * 8) =
                make_float4(acc[i][0], acc[i][1], acc[i][2], acc[i][3]);
            *(float4*)(g_h + (size_t)gr * 128 + tx * 8 + 4) =
                make_float4(acc[i][4], acc[i][5], acc[i][6], acc[i][7]);
        }
    }

    // fused alpha: this thread's 8 cols (tx*8..tx*8+7) lie in one head (tx<8 -> head0)
    float as[8], ad[8];
    *(float4*)&as[0] = *(const float4*)(attS + tx * 8);
    *(float4*)&as[4] = *(const float4*)(attS + tx * 8 + 4);
    *(float4*)&ad[0] = *(const float4*)(attD + tx * 8);
    *(float4*)&ad[4] = *(const float4*)(attD + tx * 8 + 4);
    int head = tx >> 3;
#pragma unroll
    for (int i = 0; i < 8; i++) {
        float s = 0.f, d = 0.f;
#pragma unroll
        for (int j = 0; j < 8; j++) {
            s = fmaf(acc[i][j], as[j], s);
            d = fmaf(acc[i][j], ad[j], d);
        }
#pragma unroll
        for (int o = 4; o; o >>= 1) {
            s += __shfl_xor_sync(0xFFFFFFFFu, s, o);
            d += __shfl_xor_sync(0xFFFFFFFFu, d, o);
        }
        if ((tx & 7) == 0) {
            int gr = bm + ty * 8 + i;
            if (gr < Nn) {
                g_asrc[gr * 2 + head] = s;
                g_adst[gr * 2 + head] = d;
            }
        }
    }
}

// ---------------- fused edge softmax + aggregate (warp per dst node) ----------------
__global__ void aggregate_kernel() {
    int gid  = blockIdx.x * blockDim.x + threadIdx.x;
    int n    = gid >> 5;
    if (n >= Nn) return;
    int lane = gid & 31;
    int hh   = lane >> 4;

    float ad0 = g_adst[n * 2 + 0];
    float ad1 = g_adst[n * 2 + 1];
    int start = g_rowptr[n];
    int end   = g_rowptr[n + 1];

    float z0 = 0.f, z1 = 0.f;
    float4 accA = make_float4(0.f, 0.f, 0.f, 0.f);
    float4 accB = make_float4(0.f, 0.f, 0.f, 0.f);

    for (int base = start; base < end; base += 32) {
        int i = base + lane;
        int s = 0; float p0 = 0.f, p1 = 0.f;
        if (i < end) {
            s = g_eidx[i];
            float l0 = g_asrc[s * 2 + 0] + ad0; l0 = l0 > 0.f ? l0 : 0.2f * l0;
            float l1 = g_asrc[s * 2 + 1] + ad1; l1 = l1 > 0.f ? l1 : 0.2f * l1;
            p0 = __expf(l0); p1 = __expf(l1);
            z0 += p0; z1 += p1;
        }
        int cnt = min(32, end - base);
        int j = 0;
        for (; j + 1 < cnt; j += 2) {
            int   sA  = __shfl_sync(0xFFFFFFFFu, s, j);
            float pA0 = __shfl_sync(0xFFFFFFFFu, p0, j);
            float pA1 = __shfl_sync(0xFFFFFFFFu, p1, j);
            int   sB  = __shfl_sync(0xFFFFFFFFu, s, j + 1);
            float pB0 = __shfl_sync(0xFFFFFFFFu, p0, j + 1);
            float pB1 = __shfl_sync(0xFFFFFFFFu, p1, j + 1);
            float pA = hh ? pA1 : pA0;
            float pB = hh ? pB1 : pB0;
            float4 hA = *(const float4*)(g_h + (size_t)sA * 128 + lane * 4);
            float4 hB = *(const float4*)(g_h + (size_t)sB * 128 + lane * 4);
            accA.x = fmaf(pA, hA.x, accA.x); accA.y = fmaf(pA, hA.y, accA.y);
            accA.z = fmaf(pA, hA.z, accA.z); accA.w = fmaf(pA, hA.w, accA.w);
            accB.x = fmaf(pB, hB.x, accB.x); accB.y = fmaf(pB, hB.y, accB.y);
            accB.z = fmaf(pB, hB.z, accB.z); accB.w = fmaf(pB, hB.w, accB.w);
        }
        if (j < cnt) {
            int   sA  = __shfl_sync(0xFFFFFFFFu, s, j);
            float pA0 = __shfl_sync(0xFFFFFFFFu, p0, j);
            float pA1 = __shfl_sync(0xFFFFFFFFu, p1, j);
            float pA = hh ? pA1 : pA0;
            float4 hA = *(const float4*)(g_h + (size_t)sA * 128 + lane * 4);
            accA.x = fmaf(pA, hA.x, accA.x); accA.y = fmaf(pA, hA.y, accA.y);
            accA.z = fmaf(pA, hA.z, accA.z); accA.w = fmaf(pA, hA.w, accA.w);
        }
    }
#pragma unroll
    for (int o = 16; o; o >>= 1) {
        z0 += __shfl_xor_sync(0xFFFFFFFFu, z0, o);
        z1 += __shfl_xor_sync(0xFFFFFFFFu, z1, o);
    }
    float inv = 1.0f / (hh ? z1 : z0);
    float4 r;
    r.x = (accA.x + accB.x) * inv;
    r.y = (accA.y + accB.y) * inv;
    r.z = (accA.z + accB.z) * inv;
    r.w = (accA.w + accB.w) * inv;
    *(float4*)(g_out + (size_t)n * 128 + lane * 4) = r;
}

// ---------------- pooling ----------------
__global__ void init_pool_kernel() {
    int i = blockIdx.x * blockDim.x + threadIdx.x;
    if (i < NG * 128) g_pool[i] = 0.f;
    if (i < NG) g_cnt[i] = 0.f;
}

__global__ void pool_kernel(const void* __restrict__ batch,
                            const float* __restrict__ bias2) {
    int gid  = blockIdx.x * blockDim.x + threadIdx.x;
    int n    = gid >> 5;
    int lane = gid & 31;
    if (n >= Nn) return;
    int g = loadIdx(batch, n);
    float4 v = *(const float4*)(g_out + (size_t)n * 128 + lane * 4);
    const float* bp = bias2 + lane * 4;
    v.x = eluf(v.x + bp[0]);
    v.y = eluf(v.y + bp[1]);
    v.z = eluf(v.z + bp[2]);
    v.w = eluf(v.w + bp[3]);
    red_add_v4(g_pool + g * 128 + lane * 4, v);
    if (lane == 0) atomicAdd(&g_cnt[g], 1.0f);
}

// ---------------- classifier head + softmax ----------------
__global__ void head_kernel(const float* __restrict__ lw,
                            const float* __restrict__ lb,
                            float* __restrict__ out) {
    int g = threadIdx.x;
    if (g >= NG) return;
    float inv = 1.0f / fmaxf(g_cnt[g], 1.0f);
    float lg[NCLS];
#pragma unroll
    for (int c = 0; c < NCLS; c++) lg[c] = lb[c];
    for (int k = 0; k < 128; k++) {
        float pv = g_pool[g * 128 + k] * inv;
#pragma unroll
        for (int c = 0; c < NCLS; c++) lg[c] = fmaf(pv, lw[k * NCLS + c], lg[c]);
    }
    float mx = lg[0];
#pragma unroll
    for (int c = 1; c < NCLS; c++) mx = fmaxf(mx, lg[c]);
    float ssum = 0.f;
#pragma unroll
    for (int c = 0; c < NCLS; c++) { lg[c] = __expf(lg[c] - mx); ssum += lg[c]; }
    float is = 1.0f / ssum;
#pragma unroll
    for (int c = 0; c < NCLS; c++) out[g * NCLS + c] = lg[c] * is;
}

// ---------------- launch ----------------
extern "C" void kernel_launch(void* const* d_in, const int* in_sizes, int n_in,
                              void* d_out, int out_size) {
    const float* x    = (const float*)d_in[0];
    const void*  ei   = d_in[1];
    const void*  bat  = d_in[2];
    const float* W    = (const float*)d_in[3];
    const float* asrc = (const float*)d_in[4];
    const float* adst = (const float*)d_in[5];
    const float* bias = (const float*)d_in[6];
    const float* lw   = (const float*)d_in[7];
    const float* lb   = (const float*)d_in[8];

    const int gemmBlocks     = (Nn + 127) / 128;
    const int nodeWarpBlocks = (Nn * 32 + 255) / 256;
    const int edgeBlocks     = (E2c + 255) / 256;
    const int nodeBlocks     = (Nn + 255) / 256;

    detect_kernel<<<1, 256>>>((const int*)ei);

    // CSR build (once per launch) — multi-block scan
    zero_deg_kernel<<<nodeBlocks, 256>>>();
    degree_kernel<<<edgeBlocks, 256>>>(ei);
    scan1_kernel<<<NSCANB, SCAN_BLK>>>();
    scan2_kernel<<<1, 32>>>();
    scan3_kernel<<<nodeBlocks, 256>>>();
    fill_kernel<<<edgeBlocks, 256>>>(ei);

    for (int l = 0; l < 3; l++) {
        if (l == 0)
            gemm_kernel<0><<<gemmBlocks, 256>>>(x, W, nullptr,
                                                asrc, adst);
        else
            gemm_kernel<1><<<gemmBlocks, 256>>>(nullptr, W + l * 16384,
                                                bias + (l - 1) * 128,
                                                asrc + l * 128, adst + l * 128);
        aggregate_kernel<<<nodeWarpBlocks, 256>>>();
    }
    init_pool_kernel<<<(NG * 128 + 255) / 256, 256>>>();
    pool_kernel<<<nodeWarpBlocks, 256>>>(bat, bias + 2 * 128);
    head_kernel<<<1, 64>>>(lw, lb, (float*)d_out);
}

// round 15
// speedup vs baseline: 1.2201x; 1.0626x over previous
#include <cuda_runtime.h>
#include <math.h>

#define Nn   50000
#define Ee   800000
#define E2c  850000      // E + N self-loops
#define NG   64
#define NCLS 10

#define SCAN_BLK 1024
#define NSCANB ((Nn + SCAN_BLK - 1) / SCAN_BLK)   // 49

// ---------------- device scratch ----------------
__device__ float g_h[(size_t)Nn * 128];     // per-layer GEMM output  [N,128]
__device__ float g_out[(size_t)Nn * 128];   // per-layer aggregation  [N,128] (normalized)
__device__ float g_asrc[Nn * 2];            // alpha_src  [N,H]
__device__ float g_adst[Nn * 2];            // alpha_dst  [N,H]
__device__ int   g_deg[Nn];                 // degree counts
__device__ int   g_rowptr[Nn + 1];          // CSR row offsets
__device__ int   g_cursor[Nn];              // fill cursors
__device__ int   g_eidx[E2c];               // src node per CSR slot
__device__ int   g_bsum[NSCANB];            // per-block scan totals
__device__ int   g_boff[NSCANB];            // per-block exclusive offsets
__device__ float g_pool[NG * 128];
__device__ float g_cnt[NG];
__device__ int   g_is64;

// ---------------- helpers ----------------
__device__ __forceinline__ float eluf(float v) { return v > 0.f ? v : expm1f(v); }
__device__ __forceinline__ int loadIdx(const void* p, int i) {
    if (g_is64) return (int)((const long long*)p)[i];
    return ((const int*)p)[i];
}
__device__ __forceinline__ void red_add_v4(float* dst, float4 v) {
    asm volatile("red.global.add.v4.f32 [%0], {%1,%2,%3,%4};"
                 :: "l"(dst), "f"(v.x), "f"(v.y), "f"(v.z), "f"(v.w) : "memory");
}

// ---------------- prep: zero degrees + dtype detection (fused) ----------------
__global__ void prep_kernel(const int* ei32) {
    int i = blockIdx.x * blockDim.x + threadIdx.x;
    if (i < Nn) g_deg[i] = 0;
    if (blockIdx.x == 0) {
        __shared__ int sh;
        if (threadIdx.x == 0) sh = 0;
        __syncthreads();
        int v = 0;
        for (int k = threadIdx.x; k < 2048; k += 256) v |= ei32[2 * k + 1];
        atomicOr(&sh, v);
        __syncthreads();
        if (threadIdx.x == 0) g_is64 = (sh == 0) ? 1 : 0;
    }
}

__global__ void degree_kernel(const void* __restrict__ ei) {
    int e = blockIdx.x * blockDim.x + threadIdx.x;
    if (e >= E2c) return;
    int d = (e < Ee) ? loadIdx(ei, Ee + e) : (e - Ee);
    atomicAdd(&g_deg[d], 1);
}

// multi-block scan, phase 1: per-block inclusive scan via shuffles
__global__ void scan1_kernel() {
    __shared__ int warpsums[32];
    int tid  = threadIdx.x;
    int lane = tid & 31;
    int wid  = tid >> 5;
    int idx  = blockIdx.x * SCAN_BLK + tid;
    int v = (idx < Nn) ? g_deg[idx] : 0;
    int s = v;
#pragma unroll
    for (int o = 1; o < 32; o <<= 1) {
        int t = __shfl_up_sync(0xFFFFFFFFu, s, o);
        if (lane >= o) s += t;
    }
    if (lane == 31) warpsums[wid] = s;
    __syncthreads();
    if (wid == 0) {
        int ws = warpsums[lane];
#pragma unroll
        for (int o = 1; o < 32; o <<= 1) {
            int t = __shfl_up_sync(0xFFFFFFFFu, ws, o);
            if (lane >= o) ws += t;
        }
        warpsums[lane] = ws;
    }
    __syncthreads();
    int excl = s - v + (wid ? warpsums[wid - 1] : 0);
    if (idx < Nn) g_rowptr[idx] = excl;             // block-local; offset added in phase 3
    if (tid == SCAN_BLK - 1) g_bsum[blockIdx.x] = excl + v;
}

// phase 2: scan the 49 block totals
__global__ void scan2_kernel() {
    if (threadIdx.x == 0) {
        int acc = 0;
#pragma unroll
        for (int i = 0; i < NSCANB; i++) {
            g_boff[i] = acc;
            acc += g_bsum[i];
        }
        g_rowptr[Nn] = acc;
    }
}

// phase 3: add block offsets, init cursors
__global__ void scan3_kernel() {
    int idx = blockIdx.x * blockDim.x + threadIdx.x;
    if (idx < Nn) {
        int r = g_rowptr[idx] + g_boff[idx >> 10];
        g_rowptr[idx] = r;
        g_cursor[idx] = r;
    }
}

__global__ void fill_kernel(const void* __restrict__ ei) {
    int e = blockIdx.x * blockDim.x + threadIdx.x;
    if (e >= E2c) return;
    int s, d;
    if (e < Ee) { s = loadIdx(ei, e); d = loadIdx(ei, Ee + e); }
    else        { s = e - Ee; d = s; }
    int pos = atomicAdd(&g_cursor[d], 1);
    g_eidx[pos] = s;
}

// ---------------- GEMM + fused alpha epilogue ----------------
// MODE 0: X = raw input. MODE 1: X = elu(g_out + biasPrev) (g_out pre-normalized)
template <int MODE>
__global__ void gemm_kernel(const float* __restrict__ X,
                            const float* __restrict__ Wm,
                            const float* __restrict__ biasPrev,
                            const float* __restrict__ attS,
                            const float* __restrict__ attD) {
    __shared__ float As[16][128];   // [k][m]
    __shared__ float Bs[16][128];   // [k][n]
    const int tid = threadIdx.x;
    const int bm  = blockIdx.x * 128;
    const int tx  = tid & 15;
    const int ty  = tid >> 4;
    float acc[8][8];
#pragma unroll
    for (int i = 0; i < 8; i++)
#pragma unroll
        for (int j = 0; j < 8; j++) acc[i][j] = 0.f;

    for (int k0 = 0; k0 < 128; k0 += 16) {
#pragma unroll
        for (int t = 0; t < 2; t++) {
            int e   = tid + t * 256;
            int row = e >> 2;
            int kk4 = (e & 3) << 2;
            int gr  = bm + row;
            float4 v = make_float4(0.f, 0.f, 0.f, 0.f);
            if (gr < Nn) {
                if (MODE == 0) {
                    v = *(const float4*)(X + (size_t)gr * 128 + k0 + kk4);
                } else {
                    v = *(const float4*)(g_out + (size_t)gr * 128 + k0 + kk4);
                    v.x = eluf(v.x + biasPrev[k0 + kk4 + 0]);
                    v.y = eluf(v.y + biasPrev[k0 + kk4 + 1]);
                    v.z = eluf(v.z + biasPrev[k0 + kk4 + 2]);
                    v.w = eluf(v.w + biasPrev[k0 + kk4 + 3]);
                }
            }
            As[kk4 + 0][row] = v.x;
            As[kk4 + 1][row] = v.y;
            As[kk4 + 2][row] = v.z;
            As[kk4 + 3][row] = v.w;
            int kb = e >> 5;
            int n4 = (e & 31) << 2;
            *(float4*)&Bs[kb][n4] = *(const float4*)(Wm + (size_t)(k0 + kb) * 128 + n4);
        }
        __syncthreads();
#pragma unroll
        for (int kk = 0; kk < 16; kk++) {
            float a[8], b[8];
            *(float4*)&a[0] = *(const float4*)&As[kk][ty * 8];
            *(float4*)&a[4] = *(const float4*)&As[kk][ty * 8 + 4];
            *(float4*)&b[0] = *(const float4*)&Bs[kk][tx * 8];
            *(float4*)&b[4] = *(const float4*)&Bs[kk][tx * 8 + 4];
#pragma unroll
            for (int i = 0; i < 8; i++)
#pragma unroll
                for (int j = 0; j < 8; j++)
                    acc[i][j] = fmaf(a[i], b[j], acc[i][j]);
        }
        __syncthreads();
    }

    // store h
#pragma unroll
    for (int i = 0; i < 8; i++) {
        int gr = bm + ty * 8 + i;
        if (gr < Nn) {
            *(float4*)(g_h + (size_t)gr * 128 + tx * 8) =
                make_float4(acc[i][0], acc[i][1], acc[i][2], acc[i][3]);
            *(float4*)(g_h + (size_t)gr * 128 + tx * 8 + 4) =
                make_float4(acc[i][4], acc[i][5], acc[i][6], acc[i][7]);
        }
    }

    // fused alpha: this thread's 8 cols (tx*8..tx*8+7) lie in one head (tx<8 -> head0)
    float as[8], ad[8];
    *(float4*)&as[0] = *(const float4*)(attS + tx * 8);
    *(float4*)&as[4] = *(const float4*)(attS + tx * 8 + 4);
    *(float4*)&ad[0] = *(const float4*)(attD + tx * 8);
    *(float4*)&ad[4] = *(const float4*)(attD + tx * 8 + 4);
    int head = tx >> 3;
#pragma unroll
    for (int i = 0; i < 8; i++) {
        float s = 0.f, d = 0.f;
#pragma unroll
        for (int j = 0; j < 8; j++) {
            s = fmaf(acc[i][j], as[j], s);
            d = fmaf(acc[i][j], ad[j], d);
        }
#pragma unroll
        for (int o = 4; o; o >>= 1) {
            s += __shfl_xor_sync(0xFFFFFFFFu, s, o);
            d += __shfl_xor_sync(0xFFFFFFFFu, d, o);
        }
        if ((tx & 7) == 0) {
            int gr = bm + ty * 8 + i;
            if (gr < Nn) {
                g_asrc[gr * 2 + head] = s;
                g_adst[gr * 2 + head] = d;
            }
        }
    }
}

// ---------------- fused edge softmax + aggregate (warp per dst node) ----------------
// FINAL=1: fuse bias + ELU + mean-pool accumulation, skip g_out write.
template <int FINAL>
__global__ void aggregate_kernel(const void* __restrict__ bat,
                                 const float* __restrict__ bias2) {
    __shared__ int4 stage[8][32];
    int gid  = blockIdx.x * blockDim.x + threadIdx.x;
    int n    = gid >> 5;
    if (n >= Nn) return;
    int lane = gid & 31;
    int w    = threadIdx.x >> 5;
    int hh   = lane >> 4;

    float2 adv = *(const float2*)(g_adst + n * 2);
    int start = g_rowptr[n];
    int end   = g_rowptr[n + 1];

    float z0 = 0.f, z1 = 0.f;
    float4 a0 = make_float4(0.f,0.f,0.f,0.f), a1 = a0, a2 = a0, a3 = a0;

    for (int base = start; base < end; base += 32) {
        int i = base + lane;
        int4 st = make_int4(0, 0, 0, 0);
        if (i < end) {
            int s = g_eidx[i];
            float2 av = *(const float2*)(g_asrc + s * 2);
            float l0 = av.x + adv.x; l0 = l0 > 0.f ? l0 : 0.2f * l0;
            float l1 = av.y + adv.y; l1 = l1 > 0.f ? l1 : 0.2f * l1;
            float p0 = __expf(l0), p1 = __expf(l1);
            z0 += p0; z1 += p1;
            st = make_int4(s, __float_as_int(p0), __float_as_int(p1), 0);
        }
        stage[w][lane] = st;
        __syncwarp();
        int cnt = min(32, end - base);
        int j = 0;
        for (; j + 3 < cnt; j += 4) {
            int4 eA = stage[w][j + 0];
            int4 eB = stage[w][j + 1];
            int4 eC = stage[w][j + 2];
            int4 eD = stage[w][j + 3];
            float pA = __int_as_float(hh ? eA.z : eA.y);
            float pB = __int_as_float(hh ? eB.z : eB.y);
            float pC = __int_as_float(hh ? eC.z : eC.y);
            float pD = __int_as_float(hh ? eD.z : eD.y);
            float4 hA = __ldcg((const float4*)(g_h + (size_t)eA.x * 128) + lane);
            float4 hB = __ldcg((const float4*)(g_h + (size_t)eB.x * 128) + lane);
            float4 hC = __ldcg((const float4*)(g_h + (size_t)eC.x * 128) + lane);
            float4 hD = __ldcg((const float4*)(g_h + (size_t)eD.x * 128) + lane);
            a0.x = fmaf(pA, hA.x, a0.x); a0.y = fmaf(pA, hA.y, a0.y);
            a0.z = fmaf(pA, hA.z, a0.z); a0.w = fmaf(pA, hA.w, a0.w);
            a1.x = fmaf(pB, hB.x, a1.x); a1.y = fmaf(pB, hB.y, a1.y);
            a1.z = fmaf(pB, hB.z, a1.z); a1.w = fmaf(pB, hB.w, a1.w);
            a2.x = fmaf(pC, hC.x, a2.x); a2.y = fmaf(pC, hC.y, a2.y);
            a2.z = fmaf(pC, hC.z, a2.z); a2.w = fmaf(pC, hC.w, a2.w);
            a3.x = fmaf(pD, hD.x, a3.x); a3.y = fmaf(pD, hD.y, a3.y);
            a3.z = fmaf(pD, hD.z, a3.z); a3.w = fmaf(pD, hD.w, a3.w);
        }
        for (; j < cnt; j++) {
            int4 eA = stage[w][j];
            float pA = __int_as_float(hh ? eA.z : eA.y);
            float4 hA = __ldcg((const float4*)(g_h + (size_t)eA.x * 128) + lane);
            a0.x = fmaf(pA, hA.x, a0.x); a0.y = fmaf(pA, hA.y, a0.y);
            a0.z = fmaf(pA, hA.z, a0.z); a0.w = fmaf(pA, hA.w, a0.w);
        }
        __syncwarp();
    }
#pragma unroll
    for (int o = 16; o; o >>= 1) {
        z0 += __shfl_xor_sync(0xFFFFFFFFu, z0, o);
        z1 += __shfl_xor_sync(0xFFFFFFFFu, z1, o);
    }
    float inv = 1.0f / (hh ? z1 : z0);
    float4 r;
    r.x = (a0.x + a1.x + a2.x + a3.x) * inv;
    r.y = (a0.y + a1.y + a2.y + a3.y) * inv;
    r.z = (a0.z + a1.z + a2.z + a3.z) * inv;
    r.w = (a0.w + a1.w + a2.w + a3.w) * inv;
    if (FINAL) {
        int g = loadIdx(bat, n);
        const float* bp = bias2 + lane * 4;
        r.x = eluf(r.x + bp[0]);
        r.y = eluf(r.y + bp[1]);
        r.z = eluf(r.z + bp[2]);
        r.w = eluf(r.w + bp[3]);
        red_add_v4(g_pool + g * 128 + lane * 4, r);
        if (lane == 0) atomicAdd(&g_cnt[g], 1.0f);
    } else {
        *(float4*)(g_out + (size_t)n * 128 + lane * 4) = r;
    }
}

// ---------------- pooling init ----------------
__global__ void init_pool_kernel() {
    int i = blockIdx.x * blockDim.x + threadIdx.x;
    if (i < NG * 128) g_pool[i] = 0.f;
    if (i < NG) g_cnt[i] = 0.f;
}

// ---------------- classifier head + softmax ----------------
__global__ void head_kernel(const float* __restrict__ lw,
                            const float* __restrict__ lb,
                            float* __restrict__ out) {
    int g = threadIdx.x;
    if (g >= NG) return;
    float inv = 1.0f / fmaxf(g_cnt[g], 1.0f);
    float lg[NCLS];
#pragma unroll
    for (int c = 0; c < NCLS; c++) lg[c] = lb[c];
    for (int k = 0; k < 128; k++) {
        float pv = g_pool[g * 128 + k] * inv;
#pragma unroll
        for (int c = 0; c < NCLS; c++) lg[c] = fmaf(pv, lw[k * NCLS + c], lg[c]);
    }
    float mx = lg[0];
#pragma unroll
    for (int c = 1; c < NCLS; c++) mx = fmaxf(mx, lg[c]);
    float ssum = 0.f;
#pragma unroll
    for (int c = 0; c < NCLS; c++) { lg[c] = __expf(lg[c] - mx); ssum += lg[c]; }
    float is = 1.0f / ssum;
#pragma unroll
    for (int c = 0; c < NCLS; c++) out[g * NCLS + c] = lg[c] * is;
}

// ---------------- launch ----------------
extern "C" void kernel_launch(void* const* d_in, const int* in_sizes, int n_in,
                              void* d_out, int out_size) {
    const float* x    = (const float*)d_in[0];
    const void*  ei   = d_in[1];
    const void*  bat  = d_in[2];
    const float* W    = (const float*)d_in[3];
    const float* asrc = (const float*)d_in[4];
    const float* adst = (const float*)d_in[5];
    const float* bias = (const float*)d_in[6];
    const float* lw   = (const float*)d_in[7];
    const float* lb   = (const float*)d_in[8];

    const int gemmBlocks     = (Nn + 127) / 128;
    const int nodeWarpBlocks = (Nn * 32 + 255) / 256;
    const int edgeBlocks     = (E2c + 255) / 256;
    const int nodeBlocks     = (Nn + 255) / 256;

    // launch order chosen so index 3 (ncu capture slot) = layer-0 GEMM
    prep_kernel<<<nodeBlocks, 256>>>((const int*)ei);                 // 0
    degree_kernel<<<edgeBlocks, 256>>>(ei);                           // 1
    init_pool_kernel<<<(NG * 128 + 255) / 256, 256>>>();              // 2
    gemm_kernel<0><<<gemmBlocks, 256>>>(x, W, nullptr, asrc, adst);   // 3  <- profiled
    scan1_kernel<<<NSCANB, SCAN_BLK>>>();                             // 4
    scan2_kernel<<<1, 32>>>();                                        // 5
    scan3_kernel<<<nodeBlocks, 256>>>();                              // 6
    fill_kernel<<<edgeBlocks, 256>>>(ei);                             // 7

    aggregate_kernel<0><<<nodeWarpBlocks, 256>>>(bat, nullptr);       // 8  (layer 0)

    gemm_kernel<1><<<gemmBlocks, 256>>>(nullptr, W + 16384, bias,
                                        asrc + 128, adst + 128);      // 9
    aggregate_kernel<0><<<nodeWarpBlocks, 256>>>(bat, nullptr);       // 10 (layer 1)

    gemm_kernel<1><<<gemmBlocks, 256>>>(nullptr, W + 2 * 16384, bias + 128,
                                        asrc + 2 * 128, adst + 2 * 128); // 11
    aggregate_kernel<1><<<nodeWarpBlocks, 256>>>(bat, bias + 2 * 128);   // 12 (layer 2 + pool)

    head_kernel<<<1, 64>>>(lw, lb, (float*)d_out);                    // 13
}

// round 16
// speedup vs baseline: 1.2789x; 1.0482x over previous
#include <cuda_runtime.h>
#include <math.h>

#define Nn   50000
#define Ee   800000
#define E2c  850000      // E + N self-loops
#define NG   64
#define NCLS 10

#define SCAN_BLK 1024
#define NSCANB ((Nn + SCAN_BLK - 1) / SCAN_BLK)   // 49

// ---------------- device scratch ----------------
__device__ float g_h[(size_t)Nn * 128];     // per-layer GEMM output  [N,128]
__device__ float g_out[(size_t)Nn * 128];   // per-layer aggregation  [N,128] (normalized)
__device__ float g_asrc[Nn * 2];            // alpha_src  [N,H]
__device__ float g_adst[Nn * 2];            // alpha_dst  [N,H]
__device__ int   g_deg[Nn];                 // degree counts
__device__ int   g_rowptr[Nn + 1];          // CSR row offsets
__device__ int   g_cursor[Nn];              // fill cursors
__device__ int   g_eidx[E2c];               // src node per CSR slot
__device__ int   g_bsum[NSCANB];            // per-block scan totals
__device__ int   g_boff[NSCANB];            // per-block exclusive offsets
__device__ float g_pool[NG * 128];
__device__ float g_cnt[NG];
__device__ int   g_is64;

// ---------------- helpers ----------------
__device__ __forceinline__ float eluf(float v) { return v > 0.f ? v : expm1f(v); }
__device__ __forceinline__ int loadIdx(const void* p, int i) {
    if (g_is64) return (int)((const long long*)p)[i];
    return ((const int*)p)[i];
}
__device__ __forceinline__ void red_add_v4(float* dst, float4 v) {
    asm volatile("red.global.add.v4.f32 [%0], {%1,%2,%3,%4};"
                 :: "l"(dst), "f"(v.x), "f"(v.y), "f"(v.z), "f"(v.w) : "memory");
}
__device__ __forceinline__ unsigned tf32_of(float v) {
    unsigned r; asm("cvt.rna.tf32.f32 %0, %1;" : "=r"(r) : "f"(v)); return r;
}
__device__ __forceinline__ void mma_tf32(float c[4], const unsigned a[4], const unsigned b[2]) {
    asm volatile("mma.sync.aligned.m16n8k8.row.col.f32.tf32.tf32.f32 "
                 "{%0,%1,%2,%3}, {%4,%5,%6,%7}, {%8,%9}, {%0,%1,%2,%3};"
                 : "+f"(c[0]), "+f"(c[1]), "+f"(c[2]), "+f"(c[3])
                 : "r"(a[0]), "r"(a[1]), "r"(a[2]), "r"(a[3]), "r"(b[0]), "r"(b[1]));
}

// ---------------- prep: zero degrees + dtype detection (fused) ----------------
__global__ void prep_kernel(const int* ei32) {
    int i = blockIdx.x * blockDim.x + threadIdx.x;
    if (i < Nn) g_deg[i] = 0;
    if (blockIdx.x == 0) {
        __shared__ int sh;
        if (threadIdx.x == 0) sh = 0;
        __syncthreads();
        int v = 0;
        for (int k = threadIdx.x; k < 2048; k += 256) v |= ei32[2 * k + 1];
        atomicOr(&sh, v);
        __syncthreads();
        if (threadIdx.x == 0) g_is64 = (sh == 0) ? 1 : 0;
    }
}

__global__ void degree_kernel(const void* __restrict__ ei) {
    int e = blockIdx.x * blockDim.x + threadIdx.x;
    if (e >= E2c) return;
    int d = (e < Ee) ? loadIdx(ei, Ee + e) : (e - Ee);
    atomicAdd(&g_deg[d], 1);
}

// multi-block scan, phase 1
__global__ void scan1_kernel() {
    __shared__ int warpsums[32];
    int tid  = threadIdx.x;
    int lane = tid & 31;
    int wid  = tid >> 5;
    int idx  = blockIdx.x * SCAN_BLK + tid;
    int v = (idx < Nn) ? g_deg[idx] : 0;
    int s = v;
#pragma unroll
    for (int o = 1; o < 32; o <<= 1) {
        int t = __shfl_up_sync(0xFFFFFFFFu, s, o);
        if (lane >= o) s += t;
    }
    if (lane == 31) warpsums[wid] = s;
    __syncthreads();
    if (wid == 0) {
        int ws = warpsums[lane];
#pragma unroll
        for (int o = 1; o < 32; o <<= 1) {
            int t = __shfl_up_sync(0xFFFFFFFFu, ws, o);
            if (lane >= o) ws += t;
        }
        warpsums[lane] = ws;
    }
    __syncthreads();
    int excl = s - v + (wid ? warpsums[wid - 1] : 0);
    if (idx < Nn) g_rowptr[idx] = excl;
    if (tid == SCAN_BLK - 1) g_bsum[blockIdx.x] = excl + v;
}

__global__ void scan2_kernel() {
    if (threadIdx.x == 0) {
        int acc = 0;
#pragma unroll
        for (int i = 0; i < NSCANB; i++) {
            g_boff[i] = acc;
            acc += g_bsum[i];
        }
        g_rowptr[Nn] = acc;
    }
}

__global__ void scan3_kernel() {
    int idx = blockIdx.x * blockDim.x + threadIdx.x;
    if (idx < Nn) {
        int r = g_rowptr[idx] + g_boff[idx >> 10];
        g_rowptr[idx] = r;
        g_cursor[idx] = r;
    }
}

__global__ void fill_kernel(const void* __restrict__ ei) {
    int e = blockIdx.x * blockDim.x + threadIdx.x;
    if (e >= E2c) return;
    int s, d;
    if (e < Ee) { s = loadIdx(ei, e); d = loadIdx(ei, Ee + e); }
    else        { s = e - Ee; d = s; }
    int pos = atomicAdd(&g_cursor[d], 1);
    g_eidx[pos] = s;
}

// ---------------- tf32 tensor-core GEMM + fused alpha epilogue ----------------
// h = act(X) @ W, 128x128xK128 per block, BK=32, mma.m16n8k8.tf32.
// Smem is stored PERMUTED so each mma fragment is one vectorized LDS:
//   A: [k8][mgroup(8)][lane(32)][reg(4)]  a0=(g,t) a1=(g+8,t) a2=(g,t+4) a3=(g+8,t+4)
//   B: [k8][ngroup(16)][lane(32)][reg(2)] b0=(k=t,n=g) b1=(k=t+4,n=g)
template <int MODE>
__global__ void __launch_bounds__(256, 2)
gemm_kernel(const float* __restrict__ X,
            const float* __restrict__ Wm,
            const float* __restrict__ biasPrev,
            const float* __restrict__ attS,
            const float* __restrict__ attD) {
    __shared__ unsigned As[4 * 8 * 32 * 4];    // 16 KB
    __shared__ unsigned Bs[4 * 16 * 32 * 2];   // 16 KB
    const int tid  = threadIdx.x;
    const int bm   = blockIdx.x * 128;
    const int lane = tid & 31;
    const int wid  = tid >> 5;
    const int wm   = wid & 3;       // 4 m-strips of 32 rows
    const int wn   = wid >> 2;      // 2 n-strips of 64 cols (== head)
    const int g    = lane >> 2;
    const int t    = lane & 3;

    float acc[2][8][4];
#pragma unroll
    for (int i = 0; i < 2; i++)
#pragma unroll
        for (int j = 0; j < 8; j++)
#pragma unroll
            for (int q = 0; q < 4; q++) acc[i][j][q] = 0.f;

    for (int k0 = 0; k0 < 128; k0 += 32) {
        __syncthreads();
        // ---- stage A (128 rows x 32 k), permuted + tf32 ----
#pragma unroll
        for (int q = 0; q < 4; q++) {
            int e   = tid + q * 256;        // 0..1023 float4 slots
            int r   = e >> 3;
            int kc4 = (e & 7) << 2;
            int gr  = bm + r;
            float4 v = make_float4(0.f, 0.f, 0.f, 0.f);
            if (gr < Nn) {
                if (MODE == 0) {
                    v = *(const float4*)(X + (size_t)gr * 128 + k0 + kc4);
                } else {
                    v = *(const float4*)(g_out + (size_t)gr * 128 + k0 + kc4);
                    v.x = eluf(v.x + biasPrev[k0 + kc4 + 0]);
                    v.y = eluf(v.y + biasPrev[k0 + kc4 + 1]);
                    v.z = eluf(v.z + biasPrev[k0 + kc4 + 2]);
                    v.w = eluf(v.w + biasPrev[k0 + kc4 + 3]);
                }
            }
            int k8     = kc4 >> 3;
            int khi    = (kc4 >> 2) & 1;
            int mgroup = r >> 4;
            int rg     = r & 7;
            int rhi    = (r >> 3) & 1;
            int base   = ((k8 * 8 + mgroup) * 32 + rg * 4) * 4 + khi * 2 + rhi;
            As[base + 0]  = tf32_of(v.x);
            As[base + 4]  = tf32_of(v.y);
            As[base + 8]  = tf32_of(v.z);
            As[base + 12] = tf32_of(v.w);
        }
        // ---- stage B (32 k x 128 cols), permuted + tf32 ----
#pragma unroll
        for (int q = 0; q < 4; q++) {
            int e   = tid + q * 256;
            int k   = e >> 5;
            int nc4 = (e & 31) << 2;
            float4 v = *(const float4*)(Wm + (size_t)(k0 + k) * 128 + nc4);
            int k8  = k >> 3;
            int kt  = k & 3;
            int khi = (k >> 2) & 1;
            float vv[4] = {v.x, v.y, v.z, v.w};
#pragma unroll
            for (int u = 0; u < 4; u++) {
                int n = nc4 + u;
                int addr = ((k8 * 16 + (n >> 3)) * 32 + (n & 7) * 4 + kt) * 2 + khi;
                Bs[addr] = tf32_of(vv[u]);
            }
        }
        __syncthreads();
        // ---- compute: 4 k8-steps x 16 mma ----
#pragma unroll
        for (int k8 = 0; k8 < 4; k8++) {
            unsigned Af[2][4];
            unsigned Bf[8][2];
#pragma unroll
            for (int i = 0; i < 2; i++)
                *(uint4*)Af[i] = *(const uint4*)&As[((k8 * 8 + wm * 2 + i) * 32 + lane) * 4];
#pragma unroll
            for (int j = 0; j < 8; j++)
                *(uint2*)Bf[j] = *(const uint2*)&Bs[((k8 * 16 + wn * 8 + j) * 32 + lane) * 2];
#pragma unroll
            for (int i = 0; i < 2; i++)
#pragma unroll
                for (int j = 0; j < 8; j++)
                    mma_tf32(acc[i][j], Af[i], Bf[j]);
        }
    }

    // ---- epilogue: store h + fused alpha ----
    const int colbase = wn * 64;
    float2 aS[8], aD[8];
#pragma unroll
    for (int j = 0; j < 8; j++) {
        int col = colbase + j * 8 + t * 2;
        aS[j] = *(const float2*)(attS + col);
        aD[j] = *(const float2*)(attD + col);
    }
#pragma unroll
    for (int i = 0; i < 2; i++) {
        int r0 = bm + wm * 32 + i * 16 + g;
        int r1 = r0 + 8;
#pragma unroll
        for (int j = 0; j < 8; j++) {
            int col = colbase + j * 8 + t * 2;
            if (r0 < Nn)
                *(float2*)(g_h + (size_t)r0 * 128 + col) = make_float2(acc[i][j][0], acc[i][j][1]);
            if (r1 < Nn)
                *(float2*)(g_h + (size_t)r1 * 128 + col) = make_float2(acc[i][j][2], acc[i][j][3]);
        }
        float s0 = 0.f, s1 = 0.f, d0 = 0.f, d1 = 0.f;
#pragma unroll
        for (int j = 0; j < 8; j++) {
            s0 = fmaf(acc[i][j][0], aS[j].x, s0); s0 = fmaf(acc[i][j][1], aS[j].y, s0);
            s1 = fmaf(acc[i][j][2], aS[j].x, s1); s1 = fmaf(acc[i][j][3], aS[j].y, s1);
            d0 = fmaf(acc[i][j][0], aD[j].x, d0); d0 = fmaf(acc[i][j][1], aD[j].y, d0);
            d1 = fmaf(acc[i][j][2], aD[j].x, d1); d1 = fmaf(acc[i][j][3], aD[j].y, d1);
        }
#pragma unroll
        for (int o = 1; o <= 2; o <<= 1) {
            s0 += __shfl_xor_sync(0xFFFFFFFFu, s0, o);
            s1 += __shfl_xor_sync(0xFFFFFFFFu, s1, o);
            d0 += __shfl_xor_sync(0xFFFFFFFFu, d0, o);
            d1 += __shfl_xor_sync(0xFFFFFFFFu, d1, o);
        }
        if (t == 0) {
            if (r0 < Nn) { g_asrc[r0 * 2 + wn] = s0; g_adst[r0 * 2 + wn] = d0; }
            if (r1 < Nn) { g_asrc[r1 * 2 + wn] = s1; g_adst[r1 * 2 + wn] = d1; }
        }
    }
}

// ---------------- fused edge softmax + aggregate (warp per dst node) ----------------
// FINAL=1: fuse bias + ELU + mean-pool accumulation, skip g_out write.
template <int FINAL>
__global__ void aggregate_kernel(const void* __restrict__ bat,
                                 const float* __restrict__ bias2) {
    __shared__ int4 stage[8][32];
    int gid  = blockIdx.x * blockDim.x + threadIdx.x;
    int n    = gid >> 5;
    if (n >= Nn) return;
    int lane = gid & 31;
    int w    = threadIdx.x >> 5;
    int hh   = lane >> 4;

    float2 adv = *(const float2*)(g_adst + n * 2);
    int start = g_rowptr[n];
    int end   = g_rowptr[n + 1];

    float z0 = 0.f, z1 = 0.f;
    float4 a0 = make_float4(0.f,0.f,0.f,0.f), a1 = a0, a2 = a0, a3 = a0;

    for (int base = start; base < end; base += 32) {
        int i = base + lane;
        int4 st = make_int4(0, 0, 0, 0);
        if (i < end) {
            int s = g_eidx[i];
            float2 av = *(const float2*)(g_asrc + s * 2);
            float l0 = av.x + adv.x; l0 = l0 > 0.f ? l0 : 0.2f * l0;
            float l1 = av.y + adv.y; l1 = l1 > 0.f ? l1 : 0.2f * l1;
            float p0 = __expf(l0), p1 = __expf(l1);
            z0 += p0; z1 += p1;
            st = make_int4(s, __float_as_int(p0), __float_as_int(p1), 0);
        }
        stage[w][lane] = st;
        __syncwarp();
        int cnt = min(32, end - base);
        int j = 0;
        for (; j + 3 < cnt; j += 4) {
            int4 eA = stage[w][j + 0];
            int4 eB = stage[w][j + 1];
            int4 eC = stage[w][j + 2];
            int4 eD = stage[w][j + 3];
            float pA = __int_as_float(hh ? eA.z : eA.y);
            float pB = __int_as_float(hh ? eB.z : eB.y);
            float pC = __int_as_float(hh ? eC.z : eC.y);
            float pD = __int_as_float(hh ? eD.z : eD.y);
            float4 hA = __ldcg((const float4*)(g_h + (size_t)eA.x * 128) + lane);
            float4 hB = __ldcg((const float4*)(g_h + (size_t)eB.x * 128) + lane);
            float4 hC = __ldcg((const float4*)(g_h + (size_t)eC.x * 128) + lane);
            float4 hD = __ldcg((const float4*)(g_h + (size_t)eD.x * 128) + lane);
            a0.x = fmaf(pA, hA.x, a0.x); a0.y = fmaf(pA, hA.y, a0.y);
            a0.z = fmaf(pA, hA.z, a0.z); a0.w = fmaf(pA, hA.w, a0.w);
            a1.x = fmaf(pB, hB.x, a1.x); a1.y = fmaf(pB, hB.y, a1.y);
            a1.z = fmaf(pB, hB.z, a1.z); a1.w = fmaf(pB, hB.w, a1.w);
            a2.x = fmaf(pC, hC.x, a2.x); a2.y = fmaf(pC, hC.y, a2.y);
            a2.z = fmaf(pC, hC.z, a2.z); a2.w = fmaf(pC, hC.w, a2.w);
            a3.x = fmaf(pD, hD.x, a3.x); a3.y = fmaf(pD, hD.y, a3.y);
            a3.z = fmaf(pD, hD.z, a3.z); a3.w = fmaf(pD, hD.w, a3.w);
        }
        for (; j < cnt; j++) {
            int4 eA = stage[w][j];
            float pA = __int_as_float(hh ? eA.z : eA.y);
            float4 hA = __ldcg((const float4*)(g_h + (size_t)eA.x * 128) + lane);
            a0.x = fmaf(pA, hA.x, a0.x); a0.y = fmaf(pA, hA.y, a0.y);
            a0.z = fmaf(pA, hA.z, a0.z); a0.w = fmaf(pA, hA.w, a0.w);
        }
        __syncwarp();
    }
#pragma unroll
    for (int o = 16; o; o >>= 1) {
        z0 += __shfl_xor_sync(0xFFFFFFFFu, z0, o);
        z1 += __shfl_xor_sync(0xFFFFFFFFu, z1, o);
    }
    float inv = 1.0f / (hh ? z1 : z0);
    float4 r;
    r.x = (a0.x + a1.x + a2.x + a3.x) * inv;
    r.y = (a0.y + a1.y + a2.y + a3.y) * inv;
    r.z = (a0.z + a1.z + a2.z + a3.z) * inv;
    r.w = (a0.w + a1.w + a2.w + a3.w) * inv;
    if (FINAL) {
        int g = loadIdx(bat, n);
        const float* bp = bias2 + lane * 4;
        r.x = eluf(r.x + bp[0]);
        r.y = eluf(r.y + bp[1]);
        r.z = eluf(r.z + bp[2]);
        r.w = eluf(r.w + bp[3]);
        red_add_v4(g_pool + g * 128 + lane * 4, r);
        if (lane == 0) atomicAdd(&g_cnt[g], 1.0f);
    } else {
        *(float4*)(g_out + (size_t)n * 128 + lane * 4) = r;
    }
}

// ---------------- pooling init ----------------
__global__ void init_pool_kernel() {
    int i = blockIdx.x * blockDim.x + threadIdx.x;
    if (i < NG * 128) g_pool[i] = 0.f;
    if (i < NG) g_cnt[i] = 0.f;
}

// ---------------- classifier head + softmax ----------------
__global__ void head_kernel(const float* __restrict__ lw,
                            const float* __restrict__ lb,
                            float* __restrict__ out) {
    int g = threadIdx.x;
    if (g >= NG) return;
    float inv = 1.0f / fmaxf(g_cnt[g], 1.0f);
    float lg[NCLS];
#pragma unroll
    for (int c = 0; c < NCLS; c++) lg[c] = lb[c];
    for (int k = 0; k < 128; k++) {
        float pv = g_pool[g * 128 + k] * inv;
#pragma unroll
        for (int c = 0; c < NCLS; c++) lg[c] = fmaf(pv, lw[k * NCLS + c], lg[c]);
    }
    float mx = lg[0];
#pragma unroll
    for (int c = 1; c < NCLS; c++) mx = fmaxf(mx, lg[c]);
    float ssum = 0.f;
#pragma unroll
    for (int c = 0; c < NCLS; c++) { lg[c] = __expf(lg[c] - mx); ssum += lg[c]; }
    float is = 1.0f / ssum;
#pragma unroll
    for (int c = 0; c < NCLS; c++) out[g * NCLS + c] = lg[c] * is;
}

// ---------------- launch ----------------
extern "C" void kernel_launch(void* const* d_in, const int* in_sizes, int n_in,
                              void* d_out, int out_size) {
    const float* x    = (const float*)d_in[0];
    const void*  ei   = d_in[1];
    const void*  bat  = d_in[2];
    const float* W    = (const float*)d_in[3];
    const float* asrc = (const float*)d_in[4];
    const float* adst = (const float*)d_in[5];
    const float* bias = (const float*)d_in[6];
    const float* lw   = (const float*)d_in[7];
    const float* lb   = (const float*)d_in[8];

    const int gemmBlocks     = (Nn + 127) / 128;
    const int nodeWarpBlocks = (Nn * 32 + 255) / 256;
    const int edgeBlocks     = (E2c + 255) / 256;
    const int nodeBlocks     = (Nn + 255) / 256;

    // launch order chosen so index 3 (ncu capture slot) = layer-0 GEMM
    prep_kernel<<<nodeBlocks, 256>>>((const int*)ei);                 // 0
    degree_kernel<<<edgeBlocks, 256>>>(ei);                           // 1
    init_pool_kernel<<<(NG * 128 + 255) / 256, 256>>>();              // 2
    gemm_kernel<0><<<gemmBlocks, 256>>>(x, W, nullptr, asrc, adst);   // 3  <- profiled
    scan1_kernel<<<NSCANB, SCAN_BLK>>>();                             // 4
    scan2_kernel<<<1, 32>>>();                                        // 5
    scan3_kernel<<<nodeBlocks, 256>>>();                              // 6
    fill_kernel<<<edgeBlocks, 256>>>(ei);                             // 7

    aggregate_kernel<0><<<nodeWarpBlocks, 256>>>(bat, nullptr);       // 8  (layer 0)

    gemm_kernel<1><<<gemmBlocks, 256>>>(nullptr, W + 16384, bias,
                                        asrc + 128, adst + 128);      // 9
    aggregate_kernel<0><<<nodeWarpBlocks, 256>>>(bat, nullptr);       // 10 (layer 1)

    gemm_kernel<1><<<gemmBlocks, 256>>>(nullptr, W + 2 * 16384, bias + 128,
                                        asrc + 2 * 128, adst + 2 * 128); // 11
    aggregate_kernel<1><<<nodeWarpBlocks, 256>>>(bat, bias + 2 * 128);   // 12 (layer 2 + pool)

    head_kernel<<<1, 64>>>(lw, lb, (float*)d_out);                    // 13
}

// round 17
// speedup vs baseline: 1.6138x; 1.2619x over previous
#include <cuda_runtime.h>
#include <math.h>

#define Nn   50000
#define Ee   800000
#define E2c  850000      // E + N self-loops
#define NG   64
#define NCLS 10

#define SCAN_BLK 1024
#define NSCANB ((Nn + SCAN_BLK - 1) / SCAN_BLK)   // 49

// ---------------- device scratch ----------------
__device__ float g_h[(size_t)Nn * 128];     // per-layer GEMM output  [N,128]
__device__ float g_out[(size_t)Nn * 128];   // per-layer aggregation  [N,128] (normalized)
__device__ float g_asrc[Nn * 2];            // alpha_src  [N,H]
__device__ float g_adst[Nn * 2];            // alpha_dst  [N,H]
__device__ int   g_deg[Nn];                 // degree counts
__device__ int   g_rowptr[Nn + 1];          // CSR row offsets
__device__ int   g_cursor[Nn];              // fill cursors
__device__ int   g_eidx[E2c];               // src node per CSR slot
__device__ int   g_bsum[NSCANB];            // per-block scan totals
__device__ int   g_boff[NSCANB];            // per-block exclusive offsets
__device__ unsigned g_Wp[3 * 128 * 128];    // W pre-permuted to tf32 fragment layout
__device__ float g_pool[NG * 128];
__device__ float g_cnt[NG];
__device__ int   g_is64;

// ---------------- helpers ----------------
__device__ __forceinline__ float eluf(float v) { return v > 0.f ? v : expm1f(v); }
__device__ __forceinline__ int loadIdx(const void* p, int i) {
    if (g_is64) return (int)((const long long*)p)[i];
    return ((const int*)p)[i];
}
__device__ __forceinline__ void red_add_v4(float* dst, float4 v) {
    asm volatile("red.global.add.v4.f32 [%0], {%1,%2,%3,%4};"
                 :: "l"(dst), "f"(v.x), "f"(v.y), "f"(v.z), "f"(v.w) : "memory");
}
__device__ __forceinline__ unsigned tf32_of(float v) {
    unsigned r; asm("cvt.rna.tf32.f32 %0, %1;" : "=r"(r) : "f"(v)); return r;
}
__device__ __forceinline__ void mma_tf32(float c[4], const unsigned a[4], const unsigned b[2]) {
    asm volatile("mma.sync.aligned.m16n8k8.row.col.f32.tf32.tf32.f32 "
                 "{%0,%1,%2,%3}, {%4,%5,%6,%7}, {%8,%9}, {%0,%1,%2,%3};"
                 : "+f"(c[0]), "+f"(c[1]), "+f"(c[2]), "+f"(c[3])
                 : "r"(a[0]), "r"(a[1]), "r"(a[2]), "r"(a[3]), "r"(b[0]), "r"(b[1]));
}

// ---------------- W pre-permute: [L][k][n] -> tf32 fragment layout ----------------
// addr(layer,k,n) = layer*16384 + ((k8*16 + n/8)*32 + (n&7)*4 + (k&3))*2 + ((k>>2)&1)
__global__ void wperm_kernel(const float* __restrict__ W) {
    int idx = blockIdx.x * blockDim.x + threadIdx.x;
    if (idx >= 3 * 16384) return;
    int layer = idx >> 14;
    int r = idx & 16383;
    int k = r >> 7;
    int n = r & 127;
    unsigned v = tf32_of(W[idx]);
    int addr = layer * 16384 +
               (((k >> 3) * 16 + (n >> 3)) * 32 + (n & 7) * 4 + (k & 3)) * 2 + ((k >> 2) & 1);
    g_Wp[addr] = v;
}

// ---------------- prep: zero degrees + dtype detection (fused) ----------------
__global__ void prep_kernel(const int* ei32) {
    int i = blockIdx.x * blockDim.x + threadIdx.x;
    if (i < Nn) g_deg[i] = 0;
    if (blockIdx.x == 0) {
        __shared__ int sh;
        if (threadIdx.x == 0) sh = 0;
        __syncthreads();
        int v = 0;
        for (int k = threadIdx.x; k < 2048; k += 256) v |= ei32[2 * k + 1];
        atomicOr(&sh, v);
        __syncthreads();
        if (threadIdx.x == 0) g_is64 = (sh == 0) ? 1 : 0;
    }
}

__global__ void degree_kernel(const void* __restrict__ ei) {
    int e = blockIdx.x * blockDim.x + threadIdx.x;
    if (e >= E2c) return;
    int d = (e < Ee) ? loadIdx(ei, Ee + e) : (e - Ee);
    atomicAdd(&g_deg[d], 1);
}

// multi-block scan, phase 1
__global__ void scan1_kernel() {
    __shared__ int warpsums[32];
    int tid  = threadIdx.x;
    int lane = tid & 31;
    int wid  = tid >> 5;
    int idx  = blockIdx.x * SCAN_BLK + tid;
    int v = (idx < Nn) ? g_deg[idx] : 0;
    int s = v;
#pragma unroll
    for (int o = 1; o < 32; o <<= 1) {
        int t = __shfl_up_sync(0xFFFFFFFFu, s, o);
        if (lane >= o) s += t;
    }
    if (lane == 31) warpsums[wid] = s;
    __syncthreads();
    if (wid == 0) {
        int ws = warpsums[lane];
#pragma unroll
        for (int o = 1; o < 32; o <<= 1) {
            int t = __shfl_up_sync(0xFFFFFFFFu, ws, o);
            if (lane >= o) ws += t;
        }
        warpsums[lane] = ws;
    }
    __syncthreads();
    int excl = s - v + (wid ? warpsums[wid - 1] : 0);
    if (idx < Nn) g_rowptr[idx] = excl;
    if (tid == SCAN_BLK - 1) g_bsum[blockIdx.x] = excl + v;
}

__global__ void scan2_kernel() {
    if (threadIdx.x == 0) {
        int acc = 0;
#pragma unroll
        for (int i = 0; i < NSCANB; i++) {
            g_boff[i] = acc;
            acc += g_bsum[i];
        }
        g_rowptr[Nn] = acc;
    }
}

__global__ void scan3_kernel() {
    int idx = blockIdx.x * blockDim.x + threadIdx.x;
    if (idx < Nn) {
        int r = g_rowptr[idx] + g_boff[idx >> 10];
        g_rowptr[idx] = r;
        g_cursor[idx] = r;
    }
}

__global__ void fill_kernel(const void* __restrict__ ei) {
    int e = blockIdx.x * blockDim.x + threadIdx.x;
    if (e >= E2c) return;
    int s, d;
    if (e < Ee) { s = loadIdx(ei, e); d = loadIdx(ei, Ee + e); }
    else        { s = e - Ee; d = s; }
    int pos = atomicAdd(&g_cursor[d], 1);
    g_eidx[pos] = s;
}

// ---------------- tf32 tensor-core GEMM (pipelined) + fused alpha epilogue ----------------
// A: double-buffered smem, permuted fragment layout, register-prefetched.
// B: loaded directly from g_Wp (global, L1-resident 64KB) — no staging.
template <int MODE>
__global__ void __launch_bounds__(256, 2)
gemm_kernel(const float* __restrict__ X,
            int layer,
            const float* __restrict__ biasPrev,
            const float* __restrict__ attS,
            const float* __restrict__ attD) {
    __shared__ unsigned As[2][4 * 8 * 32 * 4];   // 2 x 16 KB
    const int tid  = threadIdx.x;
    const int bm   = blockIdx.x * 128;
    const int lane = tid & 31;
    const int wid  = tid >> 5;
    const int wm   = wid & 3;       // 4 m-strips of 32 rows
    const int wn   = wid >> 2;      // 2 n-strips of 64 cols (== head)
    const int g    = lane >> 2;
    const int t    = lane & 3;
    const unsigned* __restrict__ Wp = g_Wp + layer * 16384;

    float acc[2][8][4];
#pragma unroll
    for (int i = 0; i < 2; i++)
#pragma unroll
        for (int j = 0; j < 8; j++)
#pragma unroll
            for (int q = 0; q < 4; q++) acc[i][j][q] = 0.f;

    // per-thread staging coordinates (fixed across iters)
    const int e_r   = tid >> 3;              // row 0..31 handled? no: see below
    // each thread stages 4 float4: e = tid + q*256, r = e>>3, kc4 = (e&7)<<2
    float4 pv[4];

    // ---- prefetch helpers ----
    auto loadA = [&](int it) {
#pragma unroll
        for (int q = 0; q < 4; q++) {
            int e   = tid + q * 256;
            int r   = e >> 3;
            int kc4 = (e & 7) << 2;
            int gr  = bm + r;
            float4 v = make_float4(0.f, 0.f, 0.f, 0.f);
            if (gr < Nn) {
                if (MODE == 0)
                    v = *(const float4*)(X + (size_t)gr * 128 + it * 32 + kc4);
                else
                    v = *(const float4*)(g_out + (size_t)gr * 128 + it * 32 + kc4);
            }
            pv[q] = v;
        }
    };
    auto storeA = [&](int buf, int it) {
#pragma unroll
        for (int q = 0; q < 4; q++) {
            int e   = tid + q * 256;
            int r   = e >> 3;
            int kc4 = (e & 7) << 2;
            float4 v = pv[q];
            if (MODE == 1) {
                float4 b4 = *(const float4*)(biasPrev + it * 32 + kc4);
                int gr = bm + r;
                if (gr < Nn) {
                    v.x = eluf(v.x + b4.x);
                    v.y = eluf(v.y + b4.y);
                    v.z = eluf(v.z + b4.z);
                    v.w = eluf(v.w + b4.w);
                }
            }
            int k8     = kc4 >> 3;
            int khi    = (kc4 >> 2) & 1;
            int mgroup = r >> 4;
            int rg     = r & 7;
            int rhi    = (r >> 3) & 1;
            int base   = ((k8 * 8 + mgroup) * 32 + rg * 4) * 4 + khi * 2 + rhi;
            As[buf][base + 0]  = tf32_of(v.x);
            As[buf][base + 4]  = tf32_of(v.y);
            As[buf][base + 8]  = tf32_of(v.z);
            As[buf][base + 12] = tf32_of(v.w);
        }
    };
    auto compute = [&](int buf, int it) {
#pragma unroll
        for (int kk8 = 0; kk8 < 4; kk8++) {
            int gk8 = it * 4 + kk8;
            unsigned Af[2][4];
            unsigned Bf[8][2];
#pragma unroll
            for (int i = 0; i < 2; i++)
                *(uint4*)Af[i] = *(const uint4*)&As[buf][((kk8 * 8 + wm * 2 + i) * 32 + lane) * 4];
#pragma unroll
            for (int j = 0; j < 8; j++)
                *(uint2*)Bf[j] = *(const uint2*)&Wp[((gk8 * 16 + wn * 8 + j) * 32 + lane) * 2];
#pragma unroll
            for (int i = 0; i < 2; i++)
#pragma unroll
                for (int j = 0; j < 8; j++)
                    mma_tf32(acc[i][j], Af[i], Bf[j]);
        }
    };

    // ---- pipelined main loop ----
    loadA(0);
    storeA(0, 0);
    __syncthreads();
    loadA(1);
    compute(0, 0);
    __syncthreads();
    storeA(1, 1);
    loadA(2);
    __syncthreads();
    compute(1, 1);
    __syncthreads();
    storeA(0, 2);
    loadA(3);
    __syncthreads();
    compute(0, 2);
    __syncthreads();
    storeA(1, 3);
    __syncthreads();
    compute(1, 3);

    // ---- epilogue: store h + fused alpha ----
    const int colbase = wn * 64;
    float2 aS[8], aD[8];
#pragma unroll
    for (int j = 0; j < 8; j++) {
        int col = colbase + j * 8 + t * 2;
        aS[j] = *(const float2*)(attS + col);
        aD[j] = *(const float2*)(attD + col);
    }
#pragma unroll
    for (int i = 0; i < 2; i++) {
        int r0 = bm + wm * 32 + i * 16 + g;
        int r1 = r0 + 8;
#pragma unroll
        for (int j = 0; j < 8; j++) {
            int col = colbase + j * 8 + t * 2;
            if (r0 < Nn)
                *(float2*)(g_h + (size_t)r0 * 128 + col) = make_float2(acc[i][j][0], acc[i][j][1]);
            if (r1 < Nn)
                *(float2*)(g_h + (size_t)r1 * 128 + col) = make_float2(acc[i][j][2], acc[i][j][3]);
        }
        float s0 = 0.f, s1 = 0.f, d0 = 0.f, d1 = 0.f;
#pragma unroll
        for (int j = 0; j < 8; j++) {
            s0 = fmaf(acc[i][j][0], aS[j].x, s0); s0 = fmaf(acc[i][j][1], aS[j].y, s0);
            s1 = fmaf(acc[i][j][2], aS[j].x, s1); s1 = fmaf(acc[i][j][3], aS[j].y, s1);
            d0 = fmaf(acc[i][j][0], aD[j].x, d0); d0 = fmaf(acc[i][j][1], aD[j].y, d0);
            d1 = fmaf(acc[i][j][2], aD[j].x, d1); d1 = fmaf(acc[i][j][3], aD[j].y, d1);
        }
#pragma unroll
        for (int o = 1; o <= 2; o <<= 1) {
            s0 += __shfl_xor_sync(0xFFFFFFFFu, s0, o);
            s1 += __shfl_xor_sync(0xFFFFFFFFu, s1, o);
            d0 += __shfl_xor_sync(0xFFFFFFFFu, d0, o);
            d1 += __shfl_xor_sync(0xFFFFFFFFu, d1, o);
        }
        if (t == 0) {
            if (r0 < Nn) { g_asrc[r0 * 2 + wn] = s0; g_adst[r0 * 2 + wn] = d0; }
            if (r1 < Nn) { g_asrc[r1 * 2 + wn] = s1; g_adst[r1 * 2 + wn] = d1; }
        }
    }
}

// ---------------- fused edge softmax + aggregate (warp per dst node) ----------------
template <int FINAL>
__global__ void aggregate_kernel(const void* __restrict__ bat,
                                 const float* __restrict__ bias2) {
    __shared__ int4 stage[8][32];
    int gid  = blockIdx.x * blockDim.x + threadIdx.x;
    int n    = gid >> 5;
    if (n >= Nn) return;
    int lane = gid & 31;
    int w    = threadIdx.x >> 5;
    int hh   = lane >> 4;

    float2 adv = *(const float2*)(g_adst + n * 2);
    int start = g_rowptr[n];
    int end   = g_rowptr[n + 1];

    float z0 = 0.f, z1 = 0.f;
    float4 a0 = make_float4(0.f,0.f,0.f,0.f), a1 = a0, a2 = a0, a3 = a0;

    for (int base = start; base < end; base += 32) {
        int i = base + lane;
        int4 st = make_int4(0, 0, 0, 0);
        if (i < end) {
            int s = g_eidx[i];
            float2 av = *(const float2*)(g_asrc + s * 2);
            float l0 = av.x + adv.x; l0 = l0 > 0.f ? l0 : 0.2f * l0;
            float l1 = av.y + adv.y; l1 = l1 > 0.f ? l1 : 0.2f * l1;
            float p0 = __expf(l0), p1 = __expf(l1);
            z0 += p0; z1 += p1;
            st = make_int4(s, __float_as_int(p0), __float_as_int(p1), 0);
        }
        stage[w][lane] = st;
        __syncwarp();
        int cnt = min(32, end - base);
        int j = 0;
        for (; j + 3 < cnt; j += 4) {
            int4 eA = stage[w][j + 0];
            int4 eB = stage[w][j + 1];
            int4 eC = stage[w][j + 2];
            int4 eD = stage[w][j + 3];
            float pA = __int_as_float(hh ? eA.z : eA.y);
            float pB = __int_as_float(hh ? eB.z : eB.y);
            float pC = __int_as_float(hh ? eC.z : eC.y);
            float pD = __int_as_float(hh ? eD.z : eD.y);
            float4 hA = __ldcg((const float4*)(g_h + (size_t)eA.x * 128) + lane);
            float4 hB = __ldcg((const float4*)(g_h + (size_t)eB.x * 128) + lane);
            float4 hC = __ldcg((const float4*)(g_h + (size_t)eC.x * 128) + lane);
            float4 hD = __ldcg((const float4*)(g_h + (size_t)eD.x * 128) + lane);
            a0.x = fmaf(pA, hA.x, a0.x); a0.y = fmaf(pA, hA.y, a0.y);
            a0.z = fmaf(pA, hA.z, a0.z); a0.w = fmaf(pA, hA.w, a0.w);
            a1.x = fmaf(pB, hB.x, a1.x); a1.y = fmaf(pB, hB.y, a1.y);
            a1.z = fmaf(pB, hB.z, a1.z); a1.w = fmaf(pB, hB.w, a1.w);
            a2.x = fmaf(pC, hC.x, a2.x); a2.y = fmaf(pC, hC.y, a2.y);
            a2.z = fmaf(pC, hC.z, a2.z); a2.w = fmaf(pC, hC.w, a2.w);
            a3.x = fmaf(pD, hD.x, a3.x); a3.y = fmaf(pD, hD.y, a3.y);
            a3.z = fmaf(pD, hD.z, a3.z); a3.w = fmaf(pD, hD.w, a3.w);
        }
        for (; j < cnt; j++) {
            int4 eA = stage[w][j];
            float pA = __int_as_float(hh ? eA.z : eA.y);
            float4 hA = __ldcg((const float4*)(g_h + (size_t)eA.x * 128) + lane);
            a0.x = fmaf(pA, hA.x, a0.x); a0.y = fmaf(pA, hA.y, a0.y);
            a0.z = fmaf(pA, hA.z, a0.z); a0.w = fmaf(pA, hA.w, a0.w);
        }
        __syncwarp();
    }
#pragma unroll
    for (int o = 16; o; o >>= 1) {
        z0 += __shfl_xor_sync(0xFFFFFFFFu, z0, o);
        z1 += __shfl_xor_sync(0xFFFFFFFFu, z1, o);
    }
    float inv = 1.0f / (hh ? z1 : z0);
    float4 r;
    r.x = (a0.x + a1.x + a2.x + a3.x) * inv;
    r.y = (a0.y + a1.y + a2.y + a3.y) * inv;
    r.z = (a0.z + a1.z + a2.z + a3.z) * inv;
    r.w = (a0.w + a1.w + a2.w + a3.w) * inv;
    if (FINAL) {
        int g = loadIdx(bat, n);
        const float* bp = bias2 + lane * 4;
        r.x = eluf(r.x + bp[0]);
        r.y = eluf(r.y + bp[1]);
        r.z = eluf(r.z + bp[2]);
        r.w = eluf(r.w + bp[3]);
        red_add_v4(g_pool + g * 128 + lane * 4, r);
        if (lane == 0) atomicAdd(&g_cnt[g], 1.0f);
    } else {
        *(float4*)(g_out + (size_t)n * 128 + lane * 4) = r;
    }
}

// ---------------- pooling init ----------------
__global__ void init_pool_kernel() {
    int i = blockIdx.x * blockDim.x + threadIdx.x;
    if (i < NG * 128) g_pool[i] = 0.f;
    if (i < NG) g_cnt[i] = 0.f;
}

// ---------------- classifier head + softmax ----------------
__global__ void head_kernel(const float* __restrict__ lw,
                            const float* __restrict__ lb,
                            float* __restrict__ out) {
    int g = threadIdx.x;
    if (g >= NG) return;
    float inv = 1.0f / fmaxf(g_cnt[g], 1.0f);
    float lg[NCLS];
#pragma unroll
    for (int c = 0; c < NCLS; c++) lg[c] = lb[c];
    for (int k = 0; k < 128; k++) {
        float pv = g_pool[g * 128 + k] * inv;
#pragma unroll
        for (int c = 0; c < NCLS; c++) lg[c] = fmaf(pv, lw[k * NCLS + c], lg[c]);
    }
    float mx = lg[0];
#pragma unroll
    for (int c = 1; c < NCLS; c++) mx = fmaxf(mx, lg[c]);
    float ssum = 0.f;
#pragma unroll
    for (int c = 0; c < NCLS; c++) { lg[c] = __expf(lg[c] - mx); ssum += lg[c]; }
    float is = 1.0f / ssum;
#pragma unroll
    for (int c = 0; c < NCLS; c++) out[g * NCLS + c] = lg[c] * is;
}

// ---------------- launch ----------------
extern "C" void kernel_launch(void* const* d_in, const int* in_sizes, int n_in,
                              void* d_out, int out_size) {
    const float* x    = (const float*)d_in[0];
    const void*  ei   = d_in[1];
    const void*  bat  = d_in[2];
    const float* W    = (const float*)d_in[3];
    const float* asrc = (const float*)d_in[4];
    const float* adst = (const float*)d_in[5];
    const float* bias = (const float*)d_in[6];
    const float* lw   = (const float*)d_in[7];
    const float* lb   = (const float*)d_in[8];

    const int gemmBlocks     = (Nn + 127) / 128;
    const int nodeWarpBlocks = (Nn * 32 + 255) / 256;
    const int edgeBlocks     = (E2c + 255) / 256;
    const int nodeBlocks     = (Nn + 255) / 256;

    // launch order chosen so index 3 (ncu capture slot) = layer-0 GEMM
    wperm_kernel<<<(3 * 16384 + 255) / 256, 256>>>(W);                // 0
    prep_kernel<<<nodeBlocks, 256>>>((const int*)ei);                 // 1
    degree_kernel<<<edgeBlocks, 256>>>(ei);                           // 2
    gemm_kernel<0><<<gemmBlocks, 256>>>(x, 0, nullptr, asrc, adst);   // 3  <- profiled
    scan1_kernel<<<NSCANB, SCAN_BLK>>>();                             // 4
    scan2_kernel<<<1, 32>>>();                                        // 5
    scan3_kernel<<<nodeBlocks, 256>>>();                              // 6
    fill_kernel<<<edgeBlocks, 256>>>(ei);                             // 7
    init_pool_kernel<<<(NG * 128 + 255) / 256, 256>>>();              // 8

    aggregate_kernel<0><<<nodeWarpBlocks, 256>>>(bat, nullptr);       // 9  (layer 0)

    gemm_kernel<1><<<gemmBlocks, 256>>>(nullptr, 1, bias,
                                        asrc + 128, adst + 128);      // 10
    aggregate_kernel<0><<<nodeWarpBlocks, 256>>>(bat, nullptr);       // 11 (layer 1)

    gemm_kernel<1><<<gemmBlocks, 256>>>(nullptr, 2, bias + 128,
                                        asrc + 2 * 128, adst + 2 * 128); // 12
    aggregate_kernel<1><<<nodeWarpBlocks, 256>>>(bat, bias + 2 * 128);   // 13 (layer 2 + pool)

    head_kernel<<<1, 64>>>(lw, lb, (float*)d_out);                    // 14
}